// round 11
// baseline (speedup 1.0000x reference)
#include <cuda_runtime.h>
#include <cuda_bf16.h>
#include <math.h>
#include <stdint.h>

#define B_    2
#define T_    4096
#define HID_  2048
#define H_    16
#define HKV_  4
#define D_    128
#define NB_   64
#define QKVN_ 3072
#define SCALE_ 0.088388347648318447f
#define NEG_  (-1.0e9f)
#define MTOT  (B_*T_)   // 8192

// ---------------- scratch ----------------------------------------------------
__device__ float g_qkv[(size_t)MTOT * QKVN_];
__device__ float g_att[(size_t)MTOT * HID_];
__device__ char  g_a8h[(size_t)MTOT*HID_];
__device__ char  g_a8l[(size_t)MTOT*HID_];
__device__ char  g_w1h[(size_t)QKVN_*HID_];
__device__ char  g_w1l[(size_t)QKVN_*HID_];
__device__ char  g_w2h[(size_t)HID_*HID_];
__device__ char  g_w2l[(size_t)HID_*HID_];
__device__ char  g_t8h[(size_t)MTOT*HID_];
__device__ char  g_t8l[(size_t)MTOT*HID_];
__device__ float g_sA[MTOT];
__device__ float g_sW1[QKVN_];
__device__ float g_sW2[HID_];
__device__ float g_sT[MTOT];

// ---------------- PTX helpers ----------------------------------------------
__device__ __forceinline__ uint32_t smem_u32(const void* p) {
    uint32_t a;
    asm("{ .reg .u64 t; cvta.to.shared.u64 t, %1; cvt.u32.u64 %0, t; }"
        : "=r"(a) : "l"(p));
    return a;
}

#define CP_ASYNC16(dst, src) \
    asm volatile("cp.async.cg.shared.global [%0], [%1], 16;\n" \
                 :: "r"(dst), "l"(src))
#define CP_COMMIT() asm volatile("cp.async.commit_group;\n" ::: "memory")
#define CP_WAIT(n)  asm volatile("cp.async.wait_group %0;\n" :: "n"(n) : "memory")

#define LDMATRIX_X4(r0, r1, r2, r3, addr) \
    asm volatile("ldmatrix.sync.aligned.m8n8.x4.shared.b16 {%0,%1,%2,%3}, [%4];" \
                 : "=r"(r0), "=r"(r1), "=r"(r2), "=r"(r3) : "r"(addr))

#define LDMATRIX_X2(r0, r1, addr) \
    asm volatile("ldmatrix.sync.aligned.m8n8.x2.shared.b16 {%0,%1}, [%2];" \
                 : "=r"(r0), "=r"(r1) : "r"(addr))

#define LDMATRIX_X4T(r0, r1, r2, r3, addr) \
    asm volatile("ldmatrix.sync.aligned.m8n8.x4.trans.shared.b16 {%0,%1,%2,%3}, [%4];" \
                 : "=r"(r0), "=r"(r1), "=r"(r2), "=r"(r3) : "r"(addr))

#define MMA_BF16(d, a, b0, b1) \
    asm("mma.sync.aligned.m16n8k16.row.col.f32.bf16.bf16.f32 " \
        "{%0,%1,%2,%3}, {%4,%5,%6,%7}, {%8,%9}, {%0,%1,%2,%3};" \
        : "+f"((d)[0]), "+f"((d)[1]), "+f"((d)[2]), "+f"((d)[3]) \
        : "r"((a)[0]), "r"((a)[1]), "r"((a)[2]), "r"((a)[3]), \
          "r"(b0), "r"(b1))

#define MMA_S8(d, a, b0, b1) \
    asm("mma.sync.aligned.m16n8k32.row.col.s32.s8.s8.s32 " \
        "{%0,%1,%2,%3}, {%4,%5,%6,%7}, {%8,%9}, {%0,%1,%2,%3};" \
        : "+r"((d)[0]), "+r"((d)[1]), "+r"((d)[2]), "+r"((d)[3]) \
        : "r"((a)[0]), "r"((a)[1]), "r"((a)[2]), "r"((a)[3]), \
          "r"(b0), "r"(b1))

// float4 -> bf16 hi x4 + lo x4 (attention internal)
__device__ __forceinline__ void cvt4(float4 v, uint2& H, uint2& L) {
    float a[4] = {v.x, v.y, v.z, v.w};
    __nv_bfloat16 h[4], l[4];
    #pragma unroll
    for (int j = 0; j < 4; j++) {
        h[j] = __float2bfloat16_rn(a[j]);
        l[j] = __float2bfloat16_rn(a[j] - __bfloat162float(h[j]));
    }
    union { __nv_bfloat162 b2[2]; uint2 u; } uh, ul;
    uh.b2[0] = __halves2bfloat162(h[0], h[1]);
    uh.b2[1] = __halves2bfloat162(h[2], h[3]);
    ul.b2[0] = __halves2bfloat162(l[0], l[1]);
    ul.b2[1] = __halves2bfloat162(l[2], l[3]);
    H = uh.u; L = ul.u;
}

// ---------------------------------------------------------------------------
// Per-row int8 hi/lo quantization: x ~= (s/127) * (qh + ql/256), K = 2048.
// One block per row, 256 threads x 8 elems.
// ---------------------------------------------------------------------------
__global__ void __launch_bounds__(256) quant_rows(const float* __restrict__ in,
                                                  char* __restrict__ qh,
                                                  char* __restrict__ ql,
                                                  float* __restrict__ sc)
{
    __shared__ float wmax[8];
    const int row = blockIdx.x, tid = threadIdx.x;
    const float* p = in + (size_t)row * 2048 + tid * 8;
    float4 v0 = *(const float4*)p;
    float4 v1 = *(const float4*)(p + 4);
    float a[8] = {v0.x, v0.y, v0.z, v0.w, v1.x, v1.y, v1.z, v1.w};
    float m = 0.f;
    #pragma unroll
    for (int j = 0; j < 8; j++) m = fmaxf(m, fabsf(a[j]));
    #pragma unroll
    for (int o = 16; o; o >>= 1) m = fmaxf(m, __shfl_xor_sync(0xffffffffu, m, o));
    if ((tid & 31) == 0) wmax[tid >> 5] = m;
    __syncthreads();
    float s = fmaxf(fmaxf(fmaxf(wmax[0], wmax[1]), fmaxf(wmax[2], wmax[3])),
                    fmaxf(fmaxf(wmax[4], wmax[5]), fmaxf(wmax[6], wmax[7])));
    s = fmaxf(s, 1e-30f);
    if (tid == 0) sc[row] = s;
    const float inv = 127.f / s;
    uint32_t ph[2] = {0u, 0u}, pl[2] = {0u, 0u};
    #pragma unroll
    for (int j = 0; j < 8; j++) {
        float xs = a[j] * inv;
        int q = __float2int_rn(xs);
        int l = __float2int_rn((xs - (float)q) * 256.f);
        l = max(-128, min(127, l));
        ph[j >> 2] |= (uint32_t)(q & 255) << ((j & 3) * 8);
        pl[j >> 2] |= (uint32_t)(l & 255) << ((j & 3) * 8);
    }
    *(uint2*)(qh + (size_t)row * 2048 + tid * 8) = make_uint2(ph[0], ph[1]);
    *(uint2*)(ql + (size_t)row * 2048 + tid * 8) = make_uint2(pl[0], pl[1]);
}

// ---------------------------------------------------------------------------
// INT8 GEMM: C = A*B^T via 16-bit fixed-point emulation.
// acc1 = Ah*Bh ; acc2 = Ah*Bl + Al*Bh ; C = sA*sB/127^2 * (acc1 + acc2/256).
// CTA 128x128, K-chunk 128 (s8), 8 warps (64x32), 3-stage cp.async. K = 2048.
// ---------------------------------------------------------------------------
#define GEMM_SMEM (196608 + 1024)

__global__ void __launch_bounds__(256, 1) gemm_s8(
    const char* __restrict__ Ah8, const char* __restrict__ Al8,
    const char* __restrict__ Bh8, const char* __restrict__ Bl8,
    const float* __restrict__ sA, const float* __restrict__ sB,
    float* __restrict__ C, int ldc)
{
    extern __shared__ char smem[];
    const int tid  = threadIdx.x;
    const int lane = tid & 31;
    const int wid  = tid >> 5;
    const int m0 = blockIdx.y * 128;
    const int n0 = blockIdx.x * 128;
    const int warpM = (wid >> 2) * 64;
    const int warpN = (wid & 3) * 32;

    const uint32_t sb = smem_u32(smem);
    float* sAs = (float*)(smem + 196608);
    float* sBs = sAs + 128;

    if (tid < 128) sAs[tid] = sA[m0 + tid];
    else           sBs[tid - 128] = sB[n0 + tid - 128];

    // load mapping: tile 128 rows x 128B, 1024 x 16B chunks, 4 per thread
    uint32_t soff[4]; uint32_t grow[4]; uint32_t gcol[4];
    #pragma unroll
    for (int t = 0; t < 4; t++) {
        int idx = tid + t * 256;
        int row = idx >> 3, u = idx & 7;
        uint32_t bo = (uint32_t)(row * 128 + u * 16);
        soff[t] = bo ^ ((bo >> 3) & 0x70);
        grow[t] = (uint32_t)row;
        gcol[t] = (uint32_t)(u * 16);
    }

    const char* pAh = Ah8 + (size_t)m0 * 2048;
    const char* pAl = Al8 + (size_t)m0 * 2048;
    const char* pBh = Bh8 + (size_t)n0 * 2048;
    const char* pBl = Bl8 + (size_t)n0 * 2048;

    auto load_chunk = [&](int c) {
        uint32_t base = sb + (uint32_t)(c % 3) * 65536u;
        size_t co = (size_t)c * 128;
        #pragma unroll
        for (int t = 0; t < 4; t++) {
            size_t go = (size_t)grow[t] * 2048 + co + gcol[t];
            CP_ASYNC16(base +          soff[t], pAh + go);
            CP_ASYNC16(base + 16384u + soff[t], pAl + go);
            CP_ASYNC16(base + 32768u + soff[t], pBh + go);
            CP_ASYNC16(base + 49152u + soff[t], pBl + go);
        }
        CP_COMMIT();
    };

    const uint32_t arow  = (uint32_t)(lane & 15);
    const uint32_t acolb = (uint32_t)((lane >> 4) * 16);
    const uint32_t cx    = (arow & 7) << 4;
    const uint32_t aRowOff = (uint32_t)(warpM + (int)arow) * 128;
    const uint32_t bRowOff = (uint32_t)(warpN + (int)arow) * 128;

    int acc1[4][4][4], acc2[4][4][4];
    #pragma unroll
    for (int mi = 0; mi < 4; mi++)
        #pragma unroll
        for (int ni = 0; ni < 4; ni++)
            #pragma unroll
            for (int r = 0; r < 4; r++) { acc1[mi][ni][r] = 0; acc2[mi][ni][r] = 0; }

    const int NCH = 16;   // 2048 / 128
    load_chunk(0); load_chunk(1); load_chunk(2);

    for (int c = 0; c < NCH; c++) {
        const int rem = NCH - 1 - c;
        if (rem >= 2)      { CP_WAIT(2); }
        else if (rem == 1) { CP_WAIT(1); }
        else               { CP_WAIT(0); }
        __syncthreads();

        const uint32_t base = sb + (uint32_t)(c % 3) * 65536u;
        #pragma unroll
        for (int kk = 0; kk < 4; kk++) {
            const uint32_t cb = ((uint32_t)(kk * 32) + acolb) ^ cx;
            uint32_t bh[2][4], bl[2][4];
            #pragma unroll
            for (int np = 0; np < 2; np++) {
                uint32_t ab = base + bRowOff + (uint32_t)np * 2048 + cb;
                LDMATRIX_X4(bh[np][0], bh[np][1], bh[np][2], bh[np][3], ab + 32768u);
                LDMATRIX_X4(bl[np][0], bl[np][1], bl[np][2], bl[np][3], ab + 49152u);
            }
            #pragma unroll
            for (int mi = 0; mi < 4; mi++) {
                uint32_t ah[4], al2[4];
                uint32_t aa = base + aRowOff + (uint32_t)mi * 2048 + cb;
                LDMATRIX_X4(ah[0], ah[1], ah[2], ah[3], aa);
                LDMATRIX_X4(al2[0], al2[1], al2[2], al2[3], aa + 16384u);
                #pragma unroll
                for (int ni = 0; ni < 4; ni++)
                    MMA_S8(acc1[mi][ni], ah, bh[ni >> 1][ni & 1], bh[ni >> 1][(ni & 1) + 2]);
                #pragma unroll
                for (int ni = 0; ni < 4; ni++)
                    MMA_S8(acc2[mi][ni], ah, bl[ni >> 1][ni & 1], bl[ni >> 1][(ni & 1) + 2]);
                #pragma unroll
                for (int ni = 0; ni < 4; ni++)
                    MMA_S8(acc2[mi][ni], al2, bh[ni >> 1][ni & 1], bh[ni >> 1][(ni & 1) + 2]);
            }
        }
        __syncthreads();
        if (c + 3 < NCH) load_chunk(c + 3);
    }

    // epilogue
    #pragma unroll
    for (int mi = 0; mi < 4; mi++) {
        const int rl0 = warpM + mi * 16 + (lane >> 2);
        const float s0 = sAs[rl0]     * (1.f / 16129.f);
        const float s1 = sAs[rl0 + 8] * (1.f / 16129.f);
        #pragma unroll
        for (int ni = 0; ni < 4; ni++) {
            const int cl = warpN + ni * 8 + (lane & 3) * 2;
            const float b0 = sBs[cl], b1 = sBs[cl + 1];
            float v0 = s0 * b0 * ((float)acc1[mi][ni][0] + (float)acc2[mi][ni][0] * (1.f / 256.f));
            float v1 = s0 * b1 * ((float)acc1[mi][ni][1] + (float)acc2[mi][ni][1] * (1.f / 256.f));
            float v2 = s1 * b0 * ((float)acc1[mi][ni][2] + (float)acc2[mi][ni][2] * (1.f / 256.f));
            float v3 = s1 * b1 * ((float)acc1[mi][ni][3] + (float)acc2[mi][ni][3] * (1.f / 256.f));
            *(float2*)(C + (size_t)(m0 + rl0) * ldc + n0 + cl)     = make_float2(v0, v1);
            *(float2*)(C + (size_t)(m0 + rl0 + 8) * ldc + n0 + cl) = make_float2(v2, v3);
        }
    }
}

// ---------------------------------------------------------------------------
// RoPE in-place on g_qkv
// ---------------------------------------------------------------------------
__global__ void rope_kernel(float* __restrict__ qkv,
                            const float* __restrict__ cosb,
                            const float* __restrict__ sinb)
{
    const int gw   = (blockIdx.x * blockDim.x + threadIdx.x) >> 5;
    const int lane = threadIdx.x & 31;
    const int tok  = gw / 20;
    const int hh   = gw % 20;
    if (tok >= MTOT) return;

    float* base = qkv + (size_t)tok * QKVN_ +
                  (hh < 16 ? hh * D_ : 2048 + (hh - 16) * D_);
    const float* cr = cosb + (size_t)tok * 64;
    const float* sr = sinb + (size_t)tok * 64;

    float x1 = base[lane], x2 = base[lane + 32];
    float c1 = cr[lane],  s1 = sr[lane];
    float c2 = cr[lane + 32], s2 = sr[lane + 32];
    base[lane]      = x1 * c1 - x2 * s1;
    base[lane + 32] = x2 * c2 + x1 * s2;
}

// ---------------------------------------------------------------------------
// Tensor-core block-sparse attention, bf16 hi/lo 3-term, fp32 softmax.
// Epilogue writes fp32 (quantized afterwards by quant_rows).
// ---------------------------------------------------------------------------
#define OQH 0
#define OQL 17408
#define OKH 34816
#define OKL 52224
#define OVH 69632
#define OVL 87040
#define OSX 104448          // fp32 [64][68]
#define OPH 121856          // bf16 [64][72]
#define OPL 131072
#define OALF 140288
#define OMRW 140544
#define OLRW 140800
#define ATTN_SMEM 141056

__global__ void __launch_bounds__(256) attn_kernel(const float* __restrict__ qkv,
                                                   float* __restrict__ out)
{
    extern __shared__ char smc[];
    const uint32_t sb = smem_u32(smc);
    float* Sx  = (float*)(smc + OSX);
    __nv_bfloat16* Ph = (__nv_bfloat16*)(smc + OPH);
    __nv_bfloat16* Pl = (__nv_bfloat16*)(smc + OPL);
    float* alf = (float*)(smc + OALF);
    float* mrw = (float*)(smc + OMRW);
    float* lrw = (float*)(smc + OLRW);

    const int tid  = threadIdx.x;
    const int lane = tid & 31;
    const int wid  = tid >> 5;
    const int iblk = blockIdx.x;
    const int h    = blockIdx.y;
    const int b    = blockIdx.z;
    const int hk   = h >> 2;
    const size_t tok0 = (size_t)b * T_ + (size_t)iblk * 64;

    const float* qg = qkv + tok0 * QKVN_ + h * D_;
    for (int f = tid; f < 2048; f += 256) {
        int r = f >> 5, c4 = (f & 31) * 4;
        uint2 Hv, Lv;
        cvt4(*(const float4*)(qg + (size_t)r * QKVN_ + c4), Hv, Lv);
        uint32_t off = (uint32_t)(r * 272 + c4 * 2);
        *(uint2*)(smc + OQH + off) = Hv;
        *(uint2*)(smc + OQL + off) = Lv;
    }
    if (tid < 64) { mrw[tid] = -3.0e38f; lrw[tid] = 0.f; }

    const uint32_t arow  = (uint32_t)(lane & 15);
    const uint32_t acolb = (uint32_t)((lane >> 4) * 16);
    const int qrow = lane >> 2;
    const int qcol = (lane & 3) * 2;

    const int n0 = wid * 8;
    const int miw   = wid >> 1;
    const int nhalf = (wid & 1) * 64;

    float accO[8][4];
    #pragma unroll
    for (int nt = 0; nt < 8; nt++)
        #pragma unroll
        for (int r = 0; r < 4; r++) accO[nt][r] = 0.f;

    for (int s = 0; s < 9; s++) {
        int kb = (s == 0) ? 0 : iblk - 8 + s;
        if (s > 0 && kb <= 0) continue;
        const bool selfb = (kb == iblk);

        __syncthreads();

        const size_t ktok = (size_t)b * T_ + (size_t)kb * 64;
        const float* kg = qkv + ktok * QKVN_ + 2048 + hk * D_;
        const float* vg = kg + 512;
        for (int f = tid; f < 2048; f += 256) {
            int r = f >> 5, c4 = (f & 31) * 4;
            uint32_t off = (uint32_t)(r * 272 + c4 * 2);
            uint2 Hv, Lv;
            cvt4(*(const float4*)(kg + (size_t)r * QKVN_ + c4), Hv, Lv);
            *(uint2*)(smc + OKH + off) = Hv;
            *(uint2*)(smc + OKL + off) = Lv;
            cvt4(*(const float4*)(vg + (size_t)r * QKVN_ + c4), Hv, Lv);
            *(uint2*)(smc + OVH + off) = Hv;
            *(uint2*)(smc + OVL + off) = Lv;
        }
        __syncthreads();

        float sacc[4][4];
        #pragma unroll
        for (int mi = 0; mi < 4; mi++)
            #pragma unroll
            for (int r = 0; r < 4; r++) sacc[mi][r] = 0.f;

        #pragma unroll
        for (int kk = 0; kk < 8; kk++) {
            uint32_t kbh[2], kbl[2];
            {
                uint32_t r = (uint32_t)(n0 + (lane & 7));
                uint32_t cb = (uint32_t)(kk * 32 + ((lane >> 3) & 1) * 16);
                uint32_t ad = sb + r * 272 + cb;
                LDMATRIX_X2(kbh[0], kbh[1], ad + OKH);
                LDMATRIX_X2(kbl[0], kbl[1], ad + OKL);
            }
            uint32_t qh[4][4], ql[4][4];
            #pragma unroll
            for (int mi = 0; mi < 4; mi++) {
                uint32_t ad = sb + ((uint32_t)(mi * 16) + arow) * 272 +
                              (uint32_t)(kk * 32) + acolb;
                LDMATRIX_X4(qh[mi][0], qh[mi][1], qh[mi][2], qh[mi][3], ad + OQH);
                LDMATRIX_X4(ql[mi][0], ql[mi][1], ql[mi][2], ql[mi][3], ad + OQL);
            }
            #pragma unroll
            for (int mi = 0; mi < 4; mi++) MMA_BF16(sacc[mi], qh[mi], kbh[0], kbh[1]);
            #pragma unroll
            for (int mi = 0; mi < 4; mi++) MMA_BF16(sacc[mi], ql[mi], kbh[0], kbh[1]);
            #pragma unroll
            for (int mi = 0; mi < 4; mi++) MMA_BF16(sacc[mi], qh[mi], kbl[0], kbl[1]);
        }
        #pragma unroll
        for (int mi = 0; mi < 4; mi++) {
            int r0 = mi * 16 + qrow;
            int c0 = n0 + qcol;
            float v0 = sacc[mi][0] * SCALE_;
            float v1 = sacc[mi][1] * SCALE_;
            float v2 = sacc[mi][2] * SCALE_;
            float v3 = sacc[mi][3] * SCALE_;
            if (selfb) {
                if (c0 > r0)         v0 = NEG_;
                if (c0 + 1 > r0)     v1 = NEG_;
                if (c0 > r0 + 8)     v2 = NEG_;
                if (c0 + 1 > r0 + 8) v3 = NEG_;
            }
            *(float2*)&Sx[r0 * 68 + c0]       = make_float2(v0, v1);
            *(float2*)&Sx[(r0 + 8) * 68 + c0] = make_float2(v2, v3);
        }
        __syncthreads();

        {
            const int r = tid >> 2, cg = tid & 3;
            float mold = mrw[r];
            float vals[16];
            float mx = -3.0e38f;
            #pragma unroll
            for (int j = 0; j < 16; j++) {
                vals[j] = Sx[r * 68 + cg * 16 + j];
                mx = fmaxf(mx, vals[j]);
            }
            mx = fmaxf(mx, __shfl_xor_sync(0xffffffffu, mx, 1));
            mx = fmaxf(mx, __shfl_xor_sync(0xffffffffu, mx, 2));
            float mnew = fmaxf(mold, mx);
            float al = __expf(mold - mnew);
            float ls = 0.f;
            #pragma unroll
            for (int j = 0; j < 16; j++) {
                float p = __expf(vals[j] - mnew);
                ls += p;
                __nv_bfloat16 phv = __float2bfloat16_rn(p);
                Ph[r * 72 + cg * 16 + j] = phv;
                Pl[r * 72 + cg * 16 + j] =
                    __float2bfloat16_rn(p - __bfloat162float(phv));
            }
            ls += __shfl_xor_sync(0xffffffffu, ls, 1);
            ls += __shfl_xor_sync(0xffffffffu, ls, 2);
            if (cg == 0) {
                mrw[r] = mnew;
                lrw[r] = lrw[r] * al + ls;
                alf[r] = al;
            }
        }
        __syncthreads();

        {
            float al0 = alf[miw * 16 + qrow];
            float al1 = alf[miw * 16 + qrow + 8];
            #pragma unroll
            for (int nt = 0; nt < 8; nt++) {
                accO[nt][0] *= al0; accO[nt][1] *= al0;
                accO[nt][2] *= al1; accO[nt][3] *= al1;
            }
            #pragma unroll
            for (int kk = 0; kk < 4; kk++) {
                uint32_t ph[4], pl[4];
                uint32_t ap = sb + ((uint32_t)(miw * 16) + arow) * 144 +
                              (uint32_t)(kk * 32) + acolb;
                LDMATRIX_X4(ph[0], ph[1], ph[2], ph[3], ap + OPH);
                LDMATRIX_X4(pl[0], pl[1], pl[2], pl[3], ap + OPL);
                uint32_t vrow = sb + ((uint32_t)(kk * 16) + arow) * 272;
                uint32_t vh[4][4], vl[4][4];
                #pragma unroll
                for (int nj = 0; nj < 4; nj++) {
                    uint32_t ad = vrow + (uint32_t)((nhalf + nj * 16) * 2) + acolb;
                    LDMATRIX_X4T(vh[nj][0], vh[nj][1], vh[nj][2], vh[nj][3], ad + OVH);
                    LDMATRIX_X4T(vl[nj][0], vl[nj][1], vl[nj][2], vl[nj][3], ad + OVL);
                }
                #pragma unroll
                for (int nj = 0; nj < 4; nj++) {
                    MMA_BF16(accO[2 * nj],     ph, vh[nj][0], vh[nj][1]);
                    MMA_BF16(accO[2 * nj + 1], ph, vh[nj][2], vh[nj][3]);
                }
                #pragma unroll
                for (int nj = 0; nj < 4; nj++) {
                    MMA_BF16(accO[2 * nj],     pl, vh[nj][0], vh[nj][1]);
                    MMA_BF16(accO[2 * nj + 1], pl, vh[nj][2], vh[nj][3]);
                }
                #pragma unroll
                for (int nj = 0; nj < 4; nj++) {
                    MMA_BF16(accO[2 * nj],     ph, vl[nj][0], vl[nj][1]);
                    MMA_BF16(accO[2 * nj + 1], ph, vl[nj][2], vl[nj][3]);
                }
            }
        }
    }
    __syncthreads();

    {
        int r0 = miw * 16 + qrow;
        float linv0 = 1.0f / lrw[r0];
        float linv1 = 1.0f / lrw[r0 + 8];
        size_t base0 = (tok0 + r0) * HID_ + h * D_ + nhalf;
        size_t base1 = (tok0 + r0 + 8) * HID_ + h * D_ + nhalf;
        #pragma unroll
        for (int nt = 0; nt < 8; nt++) {
            int cn = nt * 8 + qcol;
            *(float2*)(out + base0 + cn) =
                make_float2(accO[nt][0] * linv0, accO[nt][1] * linv0);
            *(float2*)(out + base1 + cn) =
                make_float2(accO[nt][2] * linv1, accO[nt][3] * linv1);
        }
    }
}

// ---------------------------------------------------------------------------
extern "C" void kernel_launch(void* const* d_in, const int* in_sizes, int n_in,
                              void* d_out, int out_size)
{
    const float* hs = (const float*)d_in[0];
    const float* cs = (const float*)d_in[1];
    const float* sn = (const float*)d_in[2];
    const float* Wq = (const float*)d_in[3];
    const float* Wk = (const float*)d_in[4];
    const float* Wv = (const float*)d_in[5];
    const float* Wo = (const float*)d_in[6];
    float* out = (float*)d_out;

    float *qkv, *att, *sA, *sW1, *sW2, *sT;
    char *a8h, *a8l, *w1h, *w1l, *w2h, *w2l, *t8h, *t8l;
    cudaGetSymbolAddress((void**)&qkv, g_qkv);
    cudaGetSymbolAddress((void**)&att, g_att);
    cudaGetSymbolAddress((void**)&a8h, g_a8h);
    cudaGetSymbolAddress((void**)&a8l, g_a8l);
    cudaGetSymbolAddress((void**)&w1h, g_w1h);
    cudaGetSymbolAddress((void**)&w1l, g_w1l);
    cudaGetSymbolAddress((void**)&w2h, g_w2h);
    cudaGetSymbolAddress((void**)&w2l, g_w2l);
    cudaGetSymbolAddress((void**)&t8h, g_t8h);
    cudaGetSymbolAddress((void**)&t8l, g_t8l);
    cudaGetSymbolAddress((void**)&sA,  g_sA);
    cudaGetSymbolAddress((void**)&sW1, g_sW1);
    cudaGetSymbolAddress((void**)&sW2, g_sW2);
    cudaGetSymbolAddress((void**)&sT,  g_sT);

    cudaFuncSetAttribute(gemm_s8, cudaFuncAttributeMaxDynamicSharedMemorySize,
                         GEMM_SMEM);
    cudaFuncSetAttribute(attn_kernel, cudaFuncAttributeMaxDynamicSharedMemorySize,
                         ATTN_SMEM);

    // quantize activations + weights (per-row, K = 2048)
    quant_rows<<<MTOT, 256>>>(hs, a8h, a8l, sA);
    quant_rows<<<2048, 256>>>(Wq, w1h, w1l, sW1);
    quant_rows<<<512, 256>>>(Wk, w1h + (size_t)2048 * 2048,
                                 w1l + (size_t)2048 * 2048, sW1 + 2048);
    quant_rows<<<512, 256>>>(Wv, w1h + (size_t)2560 * 2048,
                                 w1l + (size_t)2560 * 2048, sW1 + 2560);
    quant_rows<<<2048, 256>>>(Wo, w2h, w2l, sW2);

    // QKV projection (int8 tensor cores)
    gemm_s8<<<dim3(QKVN_ / 128, MTOT / 128), 256, GEMM_SMEM>>>(
        a8h, a8l, w1h, w1l, sA, sW1, qkv, QKVN_);

    // RoPE
    rope_kernel<<<(MTOT * 20) / 8, 256>>>(qkv, cs, sn);

    // Attention (bf16 3-term internal, fp32 out)
    attn_kernel<<<dim3(NB_, H_, B_), 256, ATTN_SMEM>>>(qkv, att);

    // quantize attention output, then Wo projection (int8)
    quant_rows<<<MTOT, 256>>>(att, t8h, t8l, sT);
    gemm_s8<<<dim3(HID_ / 128, MTOT / 128), 256, GEMM_SMEM>>>(
        t8h, t8l, w2h, w2l, sT, sW2, out, HID_);
}

// round 12
// speedup vs baseline: 2.1045x; 2.1045x over previous
#include <cuda_runtime.h>
#include <cuda_bf16.h>
#include <math.h>
#include <stdint.h>

#define B_    2
#define T_    4096
#define HID_  2048
#define H_    16
#define HKV_  4
#define D_    128
#define NB_   64
#define QKVN_ 3072
#define SCALE_ 0.088388347648318447f
#define NEG_  (-1.0e9f)
#define MTOT  (B_*T_)   // 8192

// ---------------- scratch ----------------------------------------------------
__device__ float g_qkv[(size_t)MTOT * QKVN_];
__device__ __nv_bfloat16 g_hs_hi[(size_t)MTOT*HID_];
__device__ __nv_bfloat16 g_hs_lo[(size_t)MTOT*HID_];
__device__ __nv_bfloat16 g_w1_hi[(size_t)QKVN_*HID_];
__device__ __nv_bfloat16 g_w1_lo[(size_t)QKVN_*HID_];
__device__ __nv_bfloat16 g_w2_hi[(size_t)HID_*HID_];
__device__ __nv_bfloat16 g_w2_lo[(size_t)HID_*HID_];
__device__ __nv_bfloat16 g_at_hi[(size_t)MTOT*HID_];
__device__ __nv_bfloat16 g_at_lo[(size_t)MTOT*HID_];

// ---------------- PTX helpers ----------------------------------------------
__device__ __forceinline__ uint32_t smem_u32(const void* p) {
    uint32_t a;
    asm("{ .reg .u64 t; cvta.to.shared.u64 t, %1; cvt.u32.u64 %0, t; }"
        : "=r"(a) : "l"(p));
    return a;
}

#define CP_ASYNC16(dst, src) \
    asm volatile("cp.async.cg.shared.global [%0], [%1], 16;\n" \
                 :: "r"(dst), "l"(src))
#define CP_COMMIT() asm volatile("cp.async.commit_group;\n" ::: "memory")
#define CP_WAIT(n)  asm volatile("cp.async.wait_group %0;\n" :: "n"(n) : "memory")

#define LDMATRIX_X4(r0, r1, r2, r3, addr) \
    asm volatile("ldmatrix.sync.aligned.m8n8.x4.shared.b16 {%0,%1,%2,%3}, [%4];" \
                 : "=r"(r0), "=r"(r1), "=r"(r2), "=r"(r3) : "r"(addr))

#define LDMATRIX_X2(r0, r1, addr) \
    asm volatile("ldmatrix.sync.aligned.m8n8.x2.shared.b16 {%0,%1}, [%2];" \
                 : "=r"(r0), "=r"(r1) : "r"(addr))

#define LDMATRIX_X4T(r0, r1, r2, r3, addr) \
    asm volatile("ldmatrix.sync.aligned.m8n8.x4.trans.shared.b16 {%0,%1,%2,%3}, [%4];" \
                 : "=r"(r0), "=r"(r1), "=r"(r2), "=r"(r3) : "r"(addr))

// non-volatile: register-pure, lets the compiler schedule
#define MMA_BF16(d, a, b0, b1) \
    asm("mma.sync.aligned.m16n8k16.row.col.f32.bf16.bf16.f32 " \
        "{%0,%1,%2,%3}, {%4,%5,%6,%7}, {%8,%9}, {%0,%1,%2,%3};" \
        : "+f"((d)[0]), "+f"((d)[1]), "+f"((d)[2]), "+f"((d)[3]) \
        : "r"((a)[0]), "r"((a)[1]), "r"((a)[2]), "r"((a)[3]), \
          "r"(b0), "r"(b1))

// float4 -> bf16 hi x4 + lo x4
__device__ __forceinline__ void cvt4(float4 v, uint2& H, uint2& L) {
    float a[4] = {v.x, v.y, v.z, v.w};
    __nv_bfloat16 h[4], l[4];
    #pragma unroll
    for (int j = 0; j < 4; j++) {
        h[j] = __float2bfloat16_rn(a[j]);
        l[j] = __float2bfloat16_rn(a[j] - __bfloat162float(h[j]));
    }
    union { __nv_bfloat162 b2[2]; uint2 u; } uh, ul;
    uh.b2[0] = __halves2bfloat162(h[0], h[1]);
    uh.b2[1] = __halves2bfloat162(h[2], h[3]);
    ul.b2[0] = __halves2bfloat162(l[0], l[1]);
    ul.b2[1] = __halves2bfloat162(l[2], l[3]);
    H = uh.u; L = ul.u;
}

// ---------------------------------------------------------------------------
// fp32 -> bf16 hi + residual lo, 8 elements/thread
// ---------------------------------------------------------------------------
__global__ void cvt_kernel(const float* __restrict__ in,
                           __nv_bfloat16* __restrict__ hi,
                           __nv_bfloat16* __restrict__ lo, int n)
{
    size_t i = ((size_t)blockIdx.x * blockDim.x + threadIdx.x) * 8;
    if (i >= (size_t)n) return;
    uint2 H0, L0, H1, L1;
    cvt4(*(const float4*)(in + i),     H0, L0);
    cvt4(*(const float4*)(in + i + 4), H1, L1);
    *(uint4*)(hi + i) = make_uint4(H0.x, H0.y, H1.x, H1.y);
    *(uint4*)(lo + i) = make_uint4(L0.x, L0.y, L1.x, L1.y);
}

// ---------------------------------------------------------------------------
// mma.sync bf16 GEMM: C = A*B^T, 3-term hi/lo.  BK=32, stage=32KB, 3 stages
// = 96KB -> 2 CTAs/SM.  Tile rows are 64B; swizzle chunk' = u ^ ((r>>1)&3)
// (conflict-free for both cp.async stores and fixed-chunk ldmatrix reads).
// ---------------------------------------------------------------------------
#define GEMM_SMEM (3 * 32768)

__global__ void __launch_bounds__(256, 2) gemm_bf16x3(
    const __nv_bfloat16* __restrict__ Ah, const __nv_bfloat16* __restrict__ Al,
    const __nv_bfloat16* __restrict__ Bh, const __nv_bfloat16* __restrict__ Bl,
    float* __restrict__ C, int K, int ldc)
{
    extern __shared__ char smem[];
    const int tid  = threadIdx.x;
    const int lane = tid & 31;
    const int wid  = tid >> 5;
    const int m0 = blockIdx.y * 128;
    const int n0 = blockIdx.x * 128;
    const int warpM = (wid >> 2) * 64;
    const int warpN = (wid & 3) * 32;

    const uint32_t sb = smem_u32(smem);

    // load mapping: tile = 128 rows x 64B; 4 threads/row, 2 slots/thread
    uint32_t soff[2]; uint32_t grow[2]; uint32_t gcol[2];
    #pragma unroll
    for (int t = 0; t < 2; t++) {
        int idx = tid + t * 256;          // 0..511
        int row = idx >> 2, u = idx & 3;
        soff[t] = (uint32_t)(row * 64 + ((u ^ ((row >> 1) & 3)) << 4));
        grow[t] = (uint32_t)row;
        gcol[t] = (uint32_t)(u * 16);
    }

    const int NCH = K >> 5;               // K=2048 -> 64 chunks of 32 bf16
    const size_t rs = (size_t)K * 2;
    const char* pAh = (const char*)(Ah + (size_t)m0 * K);
    const char* pAl = (const char*)(Al + (size_t)m0 * K);
    const char* pBh = (const char*)(Bh + (size_t)n0 * K);
    const char* pBl = (const char*)(Bl + (size_t)n0 * K);

    auto load_chunk = [&](int c) {
        uint32_t base = sb + (uint32_t)(c % 3) * 32768u;
        size_t co = (size_t)c * 64;       // 32 bf16 = 64 bytes per row
        #pragma unroll
        for (int t = 0; t < 2; t++) {
            size_t go = (size_t)grow[t] * rs + co + gcol[t];
            CP_ASYNC16(base +          soff[t], pAh + go);
            CP_ASYNC16(base + 8192u  + soff[t], pAl + go);
            CP_ASYNC16(base + 16384u + soff[t], pBh + go);
            CP_ASYNC16(base + 24576u + soff[t], pBl + go);
        }
        CP_COMMIT();
    };

    const uint32_t arow = (uint32_t)(lane & 15);
    const uint32_t asel = (uint32_t)(lane >> 4);     // which 16B chunk half

    float d[4][4][4];
    #pragma unroll
    for (int mi = 0; mi < 4; mi++)
        #pragma unroll
        for (int ni = 0; ni < 4; ni++)
            #pragma unroll
            for (int r = 0; r < 4; r++) d[mi][ni][r] = 0.f;

    load_chunk(0);
    if (NCH > 1) load_chunk(1);
    if (NCH > 2) load_chunk(2);

    for (int c = 0; c < NCH; c++) {
        const int rem = NCH - 1 - c;
        if (rem >= 2)      { CP_WAIT(2); }
        else if (rem == 1) { CP_WAIT(1); }
        else               { CP_WAIT(0); }
        __syncthreads();

        const uint32_t base = sb + (uint32_t)(c % 3) * 32768u;
        #pragma unroll
        for (int kk = 0; kk < 2; kk++) {
            const uint32_t cc = (uint32_t)(kk * 2) + asel;   // chunk index 0..3
            uint32_t bh[2][4], bl[2][4];
            #pragma unroll
            for (int np = 0; np < 2; np++) {
                uint32_t r = (uint32_t)(warpN + np * 16) + arow;
                uint32_t off = r * 64 + ((cc ^ ((r >> 1) & 3)) << 4);
                LDMATRIX_X4(bh[np][0], bh[np][1], bh[np][2], bh[np][3],
                            base + 16384u + off);
                LDMATRIX_X4(bl[np][0], bl[np][1], bl[np][2], bl[np][3],
                            base + 24576u + off);
            }
            #pragma unroll
            for (int mi = 0; mi < 4; mi++) {
                uint32_t r = (uint32_t)(warpM + mi * 16) + arow;
                uint32_t off = r * 64 + ((cc ^ ((r >> 1) & 3)) << 4);
                uint32_t ah[4], al2[4];
                LDMATRIX_X4(ah[0], ah[1], ah[2], ah[3], base + off);
                LDMATRIX_X4(al2[0], al2[1], al2[2], al2[3], base + 8192u + off);
                #pragma unroll
                for (int ni = 0; ni < 4; ni++) {
                    const int pj = ni >> 1, j = ni & 1;
                    MMA_BF16(d[mi][ni], ah, bh[pj][j], bh[pj][j + 2]);
                }
                #pragma unroll
                for (int ni = 0; ni < 4; ni++) {
                    const int pj = ni >> 1, j = ni & 1;
                    MMA_BF16(d[mi][ni], al2, bh[pj][j], bh[pj][j + 2]);
                }
                #pragma unroll
                for (int ni = 0; ni < 4; ni++) {
                    const int pj = ni >> 1, j = ni & 1;
                    MMA_BF16(d[mi][ni], ah, bl[pj][j], bl[pj][j + 2]);
                }
            }
        }
        __syncthreads();
        if (c + 3 < NCH) load_chunk(c + 3);
    }

    #pragma unroll
    for (int mi = 0; mi < 4; mi++) {
        const int r0 = m0 + warpM + mi * 16 + (lane >> 2);
        #pragma unroll
        for (int ni = 0; ni < 4; ni++) {
            const int cn = n0 + warpN + ni * 8 + (lane & 3) * 2;
            *(float2*)(C + (size_t)r0 * ldc + cn) =
                make_float2(d[mi][ni][0], d[mi][ni][1]);
            *(float2*)(C + (size_t)(r0 + 8) * ldc + cn) =
                make_float2(d[mi][ni][2], d[mi][ni][3]);
        }
    }
}

// ---------------------------------------------------------------------------
// RoPE in-place on g_qkv
// ---------------------------------------------------------------------------
__global__ void rope_kernel(float* __restrict__ qkv,
                            const float* __restrict__ cosb,
                            const float* __restrict__ sinb)
{
    const int gw   = (blockIdx.x * blockDim.x + threadIdx.x) >> 5;
    const int lane = threadIdx.x & 31;
    const int tok  = gw / 20;
    const int hh   = gw % 20;
    if (tok >= MTOT) return;

    float* base = qkv + (size_t)tok * QKVN_ +
                  (hh < 16 ? hh * D_ : 2048 + (hh - 16) * D_);
    const float* cr = cosb + (size_t)tok * 64;
    const float* sr = sinb + (size_t)tok * 64;

    float x1 = base[lane], x2 = base[lane + 32];
    float c1 = cr[lane],  s1 = sr[lane];
    float c2 = cr[lane + 32], s2 = sr[lane + 32];
    base[lane]      = x1 * c1 - x2 * s1;
    base[lane + 32] = x2 * c2 + x1 * s2;
}

// ---------------------------------------------------------------------------
// Tensor-core block-sparse attention, bf16 hi/lo 3-term, fp32 softmax.
// (unchanged from R8 best)
// ---------------------------------------------------------------------------
#define OQH 0
#define OQL 17408
#define OKH 34816
#define OKL 52224
#define OVH 69632
#define OVL 87040
#define OSX 104448          // fp32 [64][68]
#define OPH 121856          // bf16 [64][72]
#define OPL 131072
#define OALF 140288
#define OMRW 140544
#define OLRW 140800
#define ATTN_SMEM 141056

__global__ void __launch_bounds__(256) attn_kernel(const float* __restrict__ qkv,
                                                   __nv_bfloat16* __restrict__ outh,
                                                   __nv_bfloat16* __restrict__ outl)
{
    extern __shared__ char smc[];
    const uint32_t sb = smem_u32(smc);
    float* Sx  = (float*)(smc + OSX);
    __nv_bfloat16* Ph = (__nv_bfloat16*)(smc + OPH);
    __nv_bfloat16* Pl = (__nv_bfloat16*)(smc + OPL);
    float* alf = (float*)(smc + OALF);
    float* mrw = (float*)(smc + OMRW);
    float* lrw = (float*)(smc + OLRW);

    const int tid  = threadIdx.x;
    const int lane = tid & 31;
    const int wid  = tid >> 5;
    const int iblk = blockIdx.x;
    const int h    = blockIdx.y;
    const int b    = blockIdx.z;
    const int hk   = h >> 2;
    const size_t tok0 = (size_t)b * T_ + (size_t)iblk * 64;

    const float* qg = qkv + tok0 * QKVN_ + h * D_;
    for (int f = tid; f < 2048; f += 256) {
        int r = f >> 5, c4 = (f & 31) * 4;
        uint2 Hv, Lv;
        cvt4(*(const float4*)(qg + (size_t)r * QKVN_ + c4), Hv, Lv);
        uint32_t off = (uint32_t)(r * 272 + c4 * 2);
        *(uint2*)(smc + OQH + off) = Hv;
        *(uint2*)(smc + OQL + off) = Lv;
    }
    if (tid < 64) { mrw[tid] = -3.0e38f; lrw[tid] = 0.f; }

    const uint32_t arow  = (uint32_t)(lane & 15);
    const uint32_t acolb = (uint32_t)((lane >> 4) * 16);
    const int qrow = lane >> 2;
    const int qcol = (lane & 3) * 2;

    const int n0 = wid * 8;
    const int miw   = wid >> 1;
    const int nhalf = (wid & 1) * 64;

    float accO[8][4];
    #pragma unroll
    for (int nt = 0; nt < 8; nt++)
        #pragma unroll
        for (int r = 0; r < 4; r++) accO[nt][r] = 0.f;

    for (int s = 0; s < 9; s++) {
        int kb = (s == 0) ? 0 : iblk - 8 + s;
        if (s > 0 && kb <= 0) continue;
        const bool selfb = (kb == iblk);

        __syncthreads();

        const size_t ktok = (size_t)b * T_ + (size_t)kb * 64;
        const float* kg = qkv + ktok * QKVN_ + 2048 + hk * D_;
        const float* vg = kg + 512;
        for (int f = tid; f < 2048; f += 256) {
            int r = f >> 5, c4 = (f & 31) * 4;
            uint32_t off = (uint32_t)(r * 272 + c4 * 2);
            uint2 Hv, Lv;
            cvt4(*(const float4*)(kg + (size_t)r * QKVN_ + c4), Hv, Lv);
            *(uint2*)(smc + OKH + off) = Hv;
            *(uint2*)(smc + OKL + off) = Lv;
            cvt4(*(const float4*)(vg + (size_t)r * QKVN_ + c4), Hv, Lv);
            *(uint2*)(smc + OVH + off) = Hv;
            *(uint2*)(smc + OVL + off) = Lv;
        }
        __syncthreads();

        float sacc[4][4];
        #pragma unroll
        for (int mi = 0; mi < 4; mi++)
            #pragma unroll
            for (int r = 0; r < 4; r++) sacc[mi][r] = 0.f;

        #pragma unroll
        for (int kk = 0; kk < 8; kk++) {
            uint32_t kbh[2], kbl[2];
            {
                uint32_t r = (uint32_t)(n0 + (lane & 7));
                uint32_t cb = (uint32_t)(kk * 32 + ((lane >> 3) & 1) * 16);
                uint32_t ad = sb + r * 272 + cb;
                LDMATRIX_X2(kbh[0], kbh[1], ad + OKH);
                LDMATRIX_X2(kbl[0], kbl[1], ad + OKL);
            }
            uint32_t qh[4][4], ql[4][4];
            #pragma unroll
            for (int mi = 0; mi < 4; mi++) {
                uint32_t ad = sb + ((uint32_t)(mi * 16) + arow) * 272 +
                              (uint32_t)(kk * 32) + acolb;
                LDMATRIX_X4(qh[mi][0], qh[mi][1], qh[mi][2], qh[mi][3], ad + OQH);
                LDMATRIX_X4(ql[mi][0], ql[mi][1], ql[mi][2], ql[mi][3], ad + OQL);
            }
            #pragma unroll
            for (int mi = 0; mi < 4; mi++) MMA_BF16(sacc[mi], qh[mi], kbh[0], kbh[1]);
            #pragma unroll
            for (int mi = 0; mi < 4; mi++) MMA_BF16(sacc[mi], ql[mi], kbh[0], kbh[1]);
            #pragma unroll
            for (int mi = 0; mi < 4; mi++) MMA_BF16(sacc[mi], qh[mi], kbl[0], kbl[1]);
        }
        #pragma unroll
        for (int mi = 0; mi < 4; mi++) {
            int r0 = mi * 16 + qrow;
            int c0 = n0 + qcol;
            float v0 = sacc[mi][0] * SCALE_;
            float v1 = sacc[mi][1] * SCALE_;
            float v2 = sacc[mi][2] * SCALE_;
            float v3 = sacc[mi][3] * SCALE_;
            if (selfb) {
                if (c0 > r0)         v0 = NEG_;
                if (c0 + 1 > r0)     v1 = NEG_;
                if (c0 > r0 + 8)     v2 = NEG_;
                if (c0 + 1 > r0 + 8) v3 = NEG_;
            }
            *(float2*)&Sx[r0 * 68 + c0]       = make_float2(v0, v1);
            *(float2*)&Sx[(r0 + 8) * 68 + c0] = make_float2(v2, v3);
        }
        __syncthreads();

        {
            const int r = tid >> 2, cg = tid & 3;
            float mold = mrw[r];
            float vals[16];
            float mx = -3.0e38f;
            #pragma unroll
            for (int j = 0; j < 16; j++) {
                vals[j] = Sx[r * 68 + cg * 16 + j];
                mx = fmaxf(mx, vals[j]);
            }
            mx = fmaxf(mx, __shfl_xor_sync(0xffffffffu, mx, 1));
            mx = fmaxf(mx, __shfl_xor_sync(0xffffffffu, mx, 2));
            float mnew = fmaxf(mold, mx);
            float al = __expf(mold - mnew);
            float ls = 0.f;
            #pragma unroll
            for (int j = 0; j < 16; j++) {
                float p = __expf(vals[j] - mnew);
                ls += p;
                __nv_bfloat16 phv = __float2bfloat16_rn(p);
                Ph[r * 72 + cg * 16 + j] = phv;
                Pl[r * 72 + cg * 16 + j] =
                    __float2bfloat16_rn(p - __bfloat162float(phv));
            }
            ls += __shfl_xor_sync(0xffffffffu, ls, 1);
            ls += __shfl_xor_sync(0xffffffffu, ls, 2);
            if (cg == 0) {
                mrw[r] = mnew;
                lrw[r] = lrw[r] * al + ls;
                alf[r] = al;
            }
        }
        __syncthreads();

        {
            float al0 = alf[miw * 16 + qrow];
            float al1 = alf[miw * 16 + qrow + 8];
            #pragma unroll
            for (int nt = 0; nt < 8; nt++) {
                accO[nt][0] *= al0; accO[nt][1] *= al0;
                accO[nt][2] *= al1; accO[nt][3] *= al1;
            }
            #pragma unroll
            for (int kk = 0; kk < 4; kk++) {
                uint32_t ph[4], pl[4];
                uint32_t ap = sb + ((uint32_t)(miw * 16) + arow) * 144 +
                              (uint32_t)(kk * 32) + acolb;
                LDMATRIX_X4(ph[0], ph[1], ph[2], ph[3], ap + OPH);
                LDMATRIX_X4(pl[0], pl[1], pl[2], pl[3], ap + OPL);
                uint32_t vrow = sb + ((uint32_t)(kk * 16) + arow) * 272;
                uint32_t vh[4][4], vl[4][4];
                #pragma unroll
                for (int nj = 0; nj < 4; nj++) {
                    uint32_t ad = vrow + (uint32_t)((nhalf + nj * 16) * 2) + acolb;
                    LDMATRIX_X4T(vh[nj][0], vh[nj][1], vh[nj][2], vh[nj][3], ad + OVH);
                    LDMATRIX_X4T(vl[nj][0], vl[nj][1], vl[nj][2], vl[nj][3], ad + OVL);
                }
                #pragma unroll
                for (int nj = 0; nj < 4; nj++) {
                    MMA_BF16(accO[2 * nj],     ph, vh[nj][0], vh[nj][1]);
                    MMA_BF16(accO[2 * nj + 1], ph, vh[nj][2], vh[nj][3]);
                }
                #pragma unroll
                for (int nj = 0; nj < 4; nj++) {
                    MMA_BF16(accO[2 * nj],     pl, vh[nj][0], vh[nj][1]);
                    MMA_BF16(accO[2 * nj + 1], pl, vh[nj][2], vh[nj][3]);
                }
                #pragma unroll
                for (int nj = 0; nj < 4; nj++) {
                    MMA_BF16(accO[2 * nj],     ph, vl[nj][0], vl[nj][1]);
                    MMA_BF16(accO[2 * nj + 1], ph, vl[nj][2], vl[nj][3]);
                }
            }
        }
    }
    __syncthreads();

    {
        int r0 = miw * 16 + qrow;
        float linv0 = 1.0f / lrw[r0];
        float linv1 = 1.0f / lrw[r0 + 8];
        size_t base0 = (tok0 + r0) * HID_ + h * D_ + nhalf;
        size_t base1 = (tok0 + r0 + 8) * HID_ + h * D_ + nhalf;
        #pragma unroll
        for (int nt = 0; nt < 8; nt++) {
            int cn = nt * 8 + qcol;
            float o0 = accO[nt][0] * linv0, o1 = accO[nt][1] * linv0;
            float o2 = accO[nt][2] * linv1, o3 = accO[nt][3] * linv1;
            __nv_bfloat16 h0 = __float2bfloat16_rn(o0);
            __nv_bfloat16 h1 = __float2bfloat16_rn(o1);
            __nv_bfloat16 h2 = __float2bfloat16_rn(o2);
            __nv_bfloat16 h3 = __float2bfloat16_rn(o3);
            *(__nv_bfloat162*)(outh + base0 + cn) = __halves2bfloat162(h0, h1);
            *(__nv_bfloat162*)(outh + base1 + cn) = __halves2bfloat162(h2, h3);
            *(__nv_bfloat162*)(outl + base0 + cn) = __halves2bfloat162(
                __float2bfloat16_rn(o0 - __bfloat162float(h0)),
                __float2bfloat16_rn(o1 - __bfloat162float(h1)));
            *(__nv_bfloat162*)(outl + base1 + cn) = __halves2bfloat162(
                __float2bfloat16_rn(o2 - __bfloat162float(h2)),
                __float2bfloat16_rn(o3 - __bfloat162float(h3)));
        }
    }
}

// ---------------------------------------------------------------------------
extern "C" void kernel_launch(void* const* d_in, const int* in_sizes, int n_in,
                              void* d_out, int out_size)
{
    const float* hs = (const float*)d_in[0];
    const float* cs = (const float*)d_in[1];
    const float* sn = (const float*)d_in[2];
    const float* Wq = (const float*)d_in[3];
    const float* Wk = (const float*)d_in[4];
    const float* Wv = (const float*)d_in[5];
    const float* Wo = (const float*)d_in[6];
    float* out = (float*)d_out;

    float* qkv;
    __nv_bfloat16 *hsh, *hsl, *w1h, *w1l, *w2h, *w2l, *ath, *atl;
    cudaGetSymbolAddress((void**)&qkv, g_qkv);
    cudaGetSymbolAddress((void**)&hsh, g_hs_hi);
    cudaGetSymbolAddress((void**)&hsl, g_hs_lo);
    cudaGetSymbolAddress((void**)&w1h, g_w1_hi);
    cudaGetSymbolAddress((void**)&w1l, g_w1_lo);
    cudaGetSymbolAddress((void**)&w2h, g_w2_hi);
    cudaGetSymbolAddress((void**)&w2l, g_w2_lo);
    cudaGetSymbolAddress((void**)&ath, g_at_hi);
    cudaGetSymbolAddress((void**)&atl, g_at_lo);

    cudaFuncSetAttribute(gemm_bf16x3, cudaFuncAttributeMaxDynamicSharedMemorySize,
                         GEMM_SMEM);
    cudaFuncSetAttribute(attn_kernel, cudaFuncAttributeMaxDynamicSharedMemorySize,
                         ATTN_SMEM);

    const int nHS  = MTOT * HID_;
    const int nWq  = HID_ * HID_;
    const int nWkv = 512 * HID_;

    cvt_kernel<<<nHS / 2048, 256>>>(hs, hsh, hsl, nHS);
    cvt_kernel<<<nWq / 2048, 256>>>(Wq, w1h, w1l, nWq);
    cvt_kernel<<<nWkv / 2048, 256>>>(Wk, w1h + (size_t)2048 * HID_,
                                         w1l + (size_t)2048 * HID_, nWkv);
    cvt_kernel<<<nWkv / 2048, 256>>>(Wv, w1h + (size_t)2560 * HID_,
                                         w1l + (size_t)2560 * HID_, nWkv);
    cvt_kernel<<<nWq / 2048, 256>>>(Wo, w2h, w2l, nWq);

    // QKV projection
    gemm_bf16x3<<<dim3(QKVN_ / 128, MTOT / 128), 256, GEMM_SMEM>>>(
        hsh, hsl, w1h, w1l, qkv, HID_, QKVN_);

    // RoPE
    rope_kernel<<<(MTOT * 20) / 8, 256>>>(qkv, cs, sn);

    // Attention (emits bf16 hi/lo)
    attn_kernel<<<dim3(NB_, H_, B_), 256, ATTN_SMEM>>>(qkv, ath, atl);

    // Output projection
    gemm_bf16x3<<<dim3(HID_ / 128, MTOT / 128), 256, GEMM_SMEM>>>(
        ath, atl, w2h, w2l, out, HID_, HID_);
}

// round 16
// speedup vs baseline: 2.1779x; 1.0349x over previous
#include <cuda_runtime.h>
#include <cuda_bf16.h>
#include <math.h>
#include <stdint.h>

#define B_    2
#define T_    4096
#define HID_  2048
#define H_    16
#define HKV_  4
#define D_    128
#define NB_   64
#define QKVN_ 3072
#define SCALE_ 0.088388347648318447f
#define NEG_  (-1.0e9f)
#define MTOT  (B_*T_)   // 8192

// ---------------- scratch ----------------------------------------------------
__device__ __nv_bfloat16 g_qkv_hi[(size_t)MTOT * QKVN_];
__device__ __nv_bfloat16 g_qkv_lo[(size_t)MTOT * QKVN_];
__device__ __nv_bfloat16 g_hs_hi[(size_t)MTOT*HID_];
__device__ __nv_bfloat16 g_hs_lo[(size_t)MTOT*HID_];
__device__ __nv_bfloat16 g_w1_hi[(size_t)QKVN_*HID_];
__device__ __nv_bfloat16 g_w1_lo[(size_t)QKVN_*HID_];
__device__ __nv_bfloat16 g_w2_hi[(size_t)HID_*HID_];
__device__ __nv_bfloat16 g_w2_lo[(size_t)HID_*HID_];
__device__ __nv_bfloat16 g_at_hi[(size_t)MTOT*HID_];
__device__ __nv_bfloat16 g_at_lo[(size_t)MTOT*HID_];

// ---------------- PTX helpers ----------------------------------------------
__device__ __forceinline__ uint32_t smem_u32(const void* p) {
    uint32_t a;
    asm("{ .reg .u64 t; cvta.to.shared.u64 t, %1; cvt.u32.u64 %0, t; }"
        : "=r"(a) : "l"(p));
    return a;
}

#define CP_ASYNC16(dst, src) \
    asm volatile("cp.async.cg.shared.global [%0], [%1], 16;\n" \
                 :: "r"(dst), "l"(src))
#define CP_COMMIT() asm volatile("cp.async.commit_group;\n" ::: "memory")
#define CP_WAIT(n)  asm volatile("cp.async.wait_group %0;\n" :: "n"(n) : "memory")

#define LDMATRIX_X4(r0, r1, r2, r3, addr) \
    asm volatile("ldmatrix.sync.aligned.m8n8.x4.shared.b16 {%0,%1,%2,%3}, [%4];" \
                 : "=r"(r0), "=r"(r1), "=r"(r2), "=r"(r3) : "r"(addr))

#define LDMATRIX_X2(r0, r1, addr) \
    asm volatile("ldmatrix.sync.aligned.m8n8.x2.shared.b16 {%0,%1}, [%2];" \
                 : "=r"(r0), "=r"(r1) : "r"(addr))

#define LDMATRIX_X4T(r0, r1, r2, r3, addr) \
    asm volatile("ldmatrix.sync.aligned.m8n8.x4.trans.shared.b16 {%0,%1,%2,%3}, [%4];" \
                 : "=r"(r0), "=r"(r1), "=r"(r2), "=r"(r3) : "r"(addr))

// non-volatile: register-pure, lets the compiler schedule
#define MMA_BF16(d, a, b0, b1) \
    asm("mma.sync.aligned.m16n8k16.row.col.f32.bf16.bf16.f32 " \
        "{%0,%1,%2,%3}, {%4,%5,%6,%7}, {%8,%9}, {%0,%1,%2,%3};" \
        : "+f"((d)[0]), "+f"((d)[1]), "+f"((d)[2]), "+f"((d)[3]) \
        : "r"((a)[0]), "r"((a)[1]), "r"((a)[2]), "r"((a)[3]), \
          "r"(b0), "r"(b1))

// float4 -> bf16 hi x4 + lo x4
__device__ __forceinline__ void cvt4(float4 v, uint2& H, uint2& L) {
    float a[4] = {v.x, v.y, v.z, v.w};
    __nv_bfloat16 h[4], l[4];
    #pragma unroll
    for (int j = 0; j < 4; j++) {
        h[j] = __float2bfloat16_rn(a[j]);
        l[j] = __float2bfloat16_rn(a[j] - __bfloat162float(h[j]));
    }
    union { __nv_bfloat162 b2[2]; uint2 u; } uh, ul;
    uh.b2[0] = __halves2bfloat162(h[0], h[1]);
    uh.b2[1] = __halves2bfloat162(h[2], h[3]);
    ul.b2[0] = __halves2bfloat162(l[0], l[1]);
    ul.b2[1] = __halves2bfloat162(l[2], l[3]);
    H = uh.u; L = ul.u;
}

__device__ __forceinline__ void split2(float a, float b,
                                       __nv_bfloat162& H, __nv_bfloat162& L) {
    __nv_bfloat16 h0 = __float2bfloat16_rn(a);
    __nv_bfloat16 h1 = __float2bfloat16_rn(b);
    H = __halves2bfloat162(h0, h1);
    L = __halves2bfloat162(__float2bfloat16_rn(a - __bfloat162float(h0)),
                           __float2bfloat16_rn(b - __bfloat162float(h1)));
}

// ---------------------------------------------------------------------------
// fp32 -> bf16 hi + residual lo, 8 elements/thread
// ---------------------------------------------------------------------------
__global__ void cvt_kernel(const float* __restrict__ in,
                           __nv_bfloat16* __restrict__ hi,
                           __nv_bfloat16* __restrict__ lo, int n)
{
    size_t i = ((size_t)blockIdx.x * blockDim.x + threadIdx.x) * 8;
    if (i >= (size_t)n) return;
    uint2 H0, L0, H1, L1;
    cvt4(*(const float4*)(in + i),     H0, L0);
    cvt4(*(const float4*)(in + i + 4), H1, L1);
    *(uint4*)(hi + i) = make_uint4(H0.x, H0.y, H1.x, H1.y);
    *(uint4*)(lo + i) = make_uint4(L0.x, L0.y, L1.x, L1.y);
}

// ---------------------------------------------------------------------------
// mma.sync bf16 GEMM: C = A*B^T, 3-term hi/lo.  BK=32, 96KB smem, 2 CTAs/SM.
// Epilogue: fp32 (Cf) or bf16 hi/lo (Ch/Cl) selected by bf16out.
// ---------------------------------------------------------------------------
#define GEMM_SMEM (3 * 32768)

__global__ void __launch_bounds__(256, 2) gemm_bf16x3(
    const __nv_bfloat16* __restrict__ Ah, const __nv_bfloat16* __restrict__ Al,
    const __nv_bfloat16* __restrict__ Bh, const __nv_bfloat16* __restrict__ Bl,
    float* __restrict__ Cf,
    __nv_bfloat16* __restrict__ Ch, __nv_bfloat16* __restrict__ Cl,
    int bf16out, int K, int ldc)
{
    extern __shared__ char smem[];
    const int tid  = threadIdx.x;
    const int lane = tid & 31;
    const int wid  = tid >> 5;
    const int m0 = blockIdx.y * 128;
    const int n0 = blockIdx.x * 128;
    const int warpM = (wid >> 2) * 64;
    const int warpN = (wid & 3) * 32;

    const uint32_t sb = smem_u32(smem);

    uint32_t soff[2]; uint32_t grow[2]; uint32_t gcol[2];
    #pragma unroll
    for (int t = 0; t < 2; t++) {
        int idx = tid + t * 256;
        int row = idx >> 2, u = idx & 3;
        soff[t] = (uint32_t)(row * 64 + ((u ^ ((row >> 1) & 3)) << 4));
        grow[t] = (uint32_t)row;
        gcol[t] = (uint32_t)(u * 16);
    }

    const int NCH = K >> 5;
    const size_t rs = (size_t)K * 2;
    const char* pAh = (const char*)(Ah + (size_t)m0 * K);
    const char* pAl = (const char*)(Al + (size_t)m0 * K);
    const char* pBh = (const char*)(Bh + (size_t)n0 * K);
    const char* pBl = (const char*)(Bl + (size_t)n0 * K);

    auto load_chunk = [&](int c) {
        uint32_t base = sb + (uint32_t)(c % 3) * 32768u;
        size_t co = (size_t)c * 64;
        #pragma unroll
        for (int t = 0; t < 2; t++) {
            size_t go = (size_t)grow[t] * rs + co + gcol[t];
            CP_ASYNC16(base +          soff[t], pAh + go);
            CP_ASYNC16(base + 8192u  + soff[t], pAl + go);
            CP_ASYNC16(base + 16384u + soff[t], pBh + go);
            CP_ASYNC16(base + 24576u + soff[t], pBl + go);
        }
        CP_COMMIT();
    };

    const uint32_t arow = (uint32_t)(lane & 15);
    const uint32_t asel = (uint32_t)(lane >> 4);

    float d[4][4][4];
    #pragma unroll
    for (int mi = 0; mi < 4; mi++)
        #pragma unroll
        for (int ni = 0; ni < 4; ni++)
            #pragma unroll
            for (int r = 0; r < 4; r++) d[mi][ni][r] = 0.f;

    load_chunk(0);
    if (NCH > 1) load_chunk(1);
    if (NCH > 2) load_chunk(2);

    for (int c = 0; c < NCH; c++) {
        const int rem = NCH - 1 - c;
        if (rem >= 2)      { CP_WAIT(2); }
        else if (rem == 1) { CP_WAIT(1); }
        else               { CP_WAIT(0); }
        __syncthreads();

        const uint32_t base = sb + (uint32_t)(c % 3) * 32768u;
        #pragma unroll
        for (int kk = 0; kk < 2; kk++) {
            const uint32_t cc = (uint32_t)(kk * 2) + asel;
            uint32_t bh[2][4], bl[2][4];
            #pragma unroll
            for (int np = 0; np < 2; np++) {
                uint32_t r = (uint32_t)(warpN + np * 16) + arow;
                uint32_t off = r * 64 + ((cc ^ ((r >> 1) & 3)) << 4);
                LDMATRIX_X4(bh[np][0], bh[np][1], bh[np][2], bh[np][3],
                            base + 16384u + off);
                LDMATRIX_X4(bl[np][0], bl[np][1], bl[np][2], bl[np][3],
                            base + 24576u + off);
            }
            #pragma unroll
            for (int mi = 0; mi < 4; mi++) {
                uint32_t r = (uint32_t)(warpM + mi * 16) + arow;
                uint32_t off = r * 64 + ((cc ^ ((r >> 1) & 3)) << 4);
                uint32_t ah[4], al2[4];
                LDMATRIX_X4(ah[0], ah[1], ah[2], ah[3], base + off);
                LDMATRIX_X4(al2[0], al2[1], al2[2], al2[3], base + 8192u + off);
                #pragma unroll
                for (int ni = 0; ni < 4; ni++) {
                    const int pj = ni >> 1, j = ni & 1;
                    MMA_BF16(d[mi][ni], ah, bh[pj][j], bh[pj][j + 2]);
                }
                #pragma unroll
                for (int ni = 0; ni < 4; ni++) {
                    const int pj = ni >> 1, j = ni & 1;
                    MMA_BF16(d[mi][ni], al2, bh[pj][j], bh[pj][j + 2]);
                }
                #pragma unroll
                for (int ni = 0; ni < 4; ni++) {
                    const int pj = ni >> 1, j = ni & 1;
                    MMA_BF16(d[mi][ni], ah, bl[pj][j], bl[pj][j + 2]);
                }
            }
        }
        __syncthreads();
        if (c + 3 < NCH) load_chunk(c + 3);
    }

    if (bf16out) {
        #pragma unroll
        for (int mi = 0; mi < 4; mi++) {
            const int r0 = m0 + warpM + mi * 16 + (lane >> 2);
            #pragma unroll
            for (int ni = 0; ni < 4; ni++) {
                const int cn = n0 + warpN + ni * 8 + (lane & 3) * 2;
                __nv_bfloat162 H, L;
                split2(d[mi][ni][0], d[mi][ni][1], H, L);
                *(__nv_bfloat162*)(Ch + (size_t)r0 * ldc + cn) = H;
                *(__nv_bfloat162*)(Cl + (size_t)r0 * ldc + cn) = L;
                split2(d[mi][ni][2], d[mi][ni][3], H, L);
                *(__nv_bfloat162*)(Ch + (size_t)(r0 + 8) * ldc + cn) = H;
                *(__nv_bfloat162*)(Cl + (size_t)(r0 + 8) * ldc + cn) = L;
            }
        }
    } else {
        #pragma unroll
        for (int mi = 0; mi < 4; mi++) {
            const int r0 = m0 + warpM + mi * 16 + (lane >> 2);
            #pragma unroll
            for (int ni = 0; ni < 4; ni++) {
                const int cn = n0 + warpN + ni * 8 + (lane & 3) * 2;
                *(float2*)(Cf + (size_t)r0 * ldc + cn) =
                    make_float2(d[mi][ni][0], d[mi][ni][1]);
                *(float2*)(Cf + (size_t)(r0 + 8) * ldc + cn) =
                    make_float2(d[mi][ni][2], d[mi][ni][3]);
            }
        }
    }
}

// ---------------------------------------------------------------------------
// RoPE in-place on qkv hi/lo pair (first 64 dims of q heads + k heads)
// ---------------------------------------------------------------------------
__global__ void rope_kernel(__nv_bfloat16* __restrict__ qh,
                            __nv_bfloat16* __restrict__ ql,
                            const float* __restrict__ cosb,
                            const float* __restrict__ sinb)
{
    const int gw   = (blockIdx.x * blockDim.x + threadIdx.x) >> 5;
    const int lane = threadIdx.x & 31;
    const int tok  = gw / 20;
    const int hh   = gw % 20;
    if (tok >= MTOT) return;

    size_t base = (size_t)tok * QKVN_ +
                  (hh < 16 ? hh * D_ : 2048 + (hh - 16) * D_);
    const float* cr = cosb + (size_t)tok * 64;
    const float* sr = sinb + (size_t)tok * 64;

    float x1 = __bfloat162float(qh[base + lane]) +
               __bfloat162float(ql[base + lane]);
    float x2 = __bfloat162float(qh[base + lane + 32]) +
               __bfloat162float(ql[base + lane + 32]);
    float c1 = cr[lane],  s1 = sr[lane];
    float c2 = cr[lane + 32], s2 = sr[lane + 32];
    float y1 = x1 * c1 - x2 * s1;
    float y2 = x2 * c2 + x1 * s2;

    __nv_bfloat16 h1 = __float2bfloat16_rn(y1);
    __nv_bfloat16 h2 = __float2bfloat16_rn(y2);
    qh[base + lane]      = h1;
    ql[base + lane]      = __float2bfloat16_rn(y1 - __bfloat162float(h1));
    qh[base + lane + 32] = h2;
    ql[base + lane + 32] = __float2bfloat16_rn(y2 - __bfloat162float(h2));
}

// ---------------------------------------------------------------------------
// Tensor-core block-sparse attention, bf16 hi/lo 3-term, fp32 softmax.
// Q/K/V tiles loaded via cp.async directly from hi/lo qkv (no conversion).
// ---------------------------------------------------------------------------
#define OQH 0
#define OQL 17408
#define OKH 34816
#define OKL 52224
#define OVH 69632
#define OVL 87040
#define OSX 104448          // fp32 [64][68]
#define OPH 121856          // bf16 [64][72]
#define OPL 131072
#define OALF 140288
#define OMRW 140544
#define OLRW 140800
#define ATTN_SMEM 141056

__global__ void __launch_bounds__(256) attn_kernel(
    const __nv_bfloat16* __restrict__ qkvh,
    const __nv_bfloat16* __restrict__ qkvl,
    __nv_bfloat16* __restrict__ outh,
    __nv_bfloat16* __restrict__ outl)
{
    extern __shared__ char smc[];
    const uint32_t sb = smem_u32(smc);
    float* Sx  = (float*)(smc + OSX);
    __nv_bfloat16* Ph = (__nv_bfloat16*)(smc + OPH);
    __nv_bfloat16* Pl = (__nv_bfloat16*)(smc + OPL);
    float* alf = (float*)(smc + OALF);
    float* mrw = (float*)(smc + OMRW);
    float* lrw = (float*)(smc + OLRW);

    const int tid  = threadIdx.x;
    const int lane = tid & 31;
    const int wid  = tid >> 5;
    const int iblk = blockIdx.x;
    const int h    = blockIdx.y;
    const int b    = blockIdx.z;
    const int hk   = h >> 2;
    const size_t tok0 = (size_t)b * T_ + (size_t)iblk * 64;

    // ---- Q tile: cp.async 16B chunks, rows padded to 272B ----
    {
        const char* qgh = (const char*)(qkvh + tok0 * QKVN_ + h * D_);
        const char* qgl = (const char*)(qkvl + tok0 * QKVN_ + h * D_);
        for (int f = tid; f < 1024; f += 256) {
            int r = f >> 4, c16 = (f & 15) * 16;
            uint32_t off = (uint32_t)(r * 272 + c16);
            size_t go = (size_t)r * (QKVN_ * 2) + c16;
            CP_ASYNC16(sb + OQH + off, qgh + go);
            CP_ASYNC16(sb + OQL + off, qgl + go);
        }
        CP_COMMIT();
    }
    if (tid < 64) { mrw[tid] = -3.0e38f; lrw[tid] = 0.f; }

    const uint32_t arow  = (uint32_t)(lane & 15);
    const uint32_t acolb = (uint32_t)((lane >> 4) * 16);
    const int qrow = lane >> 2;
    const int qcol = (lane & 3) * 2;

    const int n0 = wid * 8;
    const int miw   = wid >> 1;
    const int nhalf = (wid & 1) * 64;

    float accO[8][4];
    #pragma unroll
    for (int nt = 0; nt < 8; nt++)
        #pragma unroll
        for (int r = 0; r < 4; r++) accO[nt][r] = 0.f;

    for (int s = 0; s < 9; s++) {
        int kb = (s == 0) ? 0 : iblk - 8 + s;
        if (s > 0 && kb <= 0) continue;
        const bool selfb = (kb == iblk);

        __syncthreads();   // prior PV reads done before K/V overwrite

        const size_t ktok = (size_t)b * T_ + (size_t)kb * 64;
        const char* kgh = (const char*)(qkvh + ktok * QKVN_ + 2048 + hk * D_);
        const char* kgl = (const char*)(qkvl + ktok * QKVN_ + 2048 + hk * D_);
        const char* vgh = kgh + 1024;   // v head = +512 elements = +1024 bytes
        const char* vgl = kgl + 1024;
        for (int f = tid; f < 1024; f += 256) {
            int r = f >> 4, c16 = (f & 15) * 16;
            uint32_t off = (uint32_t)(r * 272 + c16);
            size_t go = (size_t)r * (QKVN_ * 2) + c16;
            CP_ASYNC16(sb + OKH + off, kgh + go);
            CP_ASYNC16(sb + OKL + off, kgl + go);
            CP_ASYNC16(sb + OVH + off, vgh + go);
            CP_ASYNC16(sb + OVL + off, vgl + go);
        }
        CP_COMMIT();
        CP_WAIT(0);
        __syncthreads();

        // ---- QK^T, term-major ----
        float sacc[4][4];
        #pragma unroll
        for (int mi = 0; mi < 4; mi++)
            #pragma unroll
            for (int r = 0; r < 4; r++) sacc[mi][r] = 0.f;

        #pragma unroll
        for (int kk = 0; kk < 8; kk++) {
            uint32_t kbh[2], kbl[2];
            {
                uint32_t r = (uint32_t)(n0 + (lane & 7));
                uint32_t cb = (uint32_t)(kk * 32 + ((lane >> 3) & 1) * 16);
                uint32_t ad = sb + r * 272 + cb;
                LDMATRIX_X2(kbh[0], kbh[1], ad + OKH);
                LDMATRIX_X2(kbl[0], kbl[1], ad + OKL);
            }
            uint32_t qh[4][4], ql[4][4];
            #pragma unroll
            for (int mi = 0; mi < 4; mi++) {
                uint32_t ad = sb + ((uint32_t)(mi * 16) + arow) * 272 +
                              (uint32_t)(kk * 32) + acolb;
                LDMATRIX_X4(qh[mi][0], qh[mi][1], qh[mi][2], qh[mi][3], ad + OQH);
                LDMATRIX_X4(ql[mi][0], ql[mi][1], ql[mi][2], ql[mi][3], ad + OQL);
            }
            #pragma unroll
            for (int mi = 0; mi < 4; mi++) MMA_BF16(sacc[mi], qh[mi], kbh[0], kbh[1]);
            #pragma unroll
            for (int mi = 0; mi < 4; mi++) MMA_BF16(sacc[mi], ql[mi], kbh[0], kbh[1]);
            #pragma unroll
            for (int mi = 0; mi < 4; mi++) MMA_BF16(sacc[mi], qh[mi], kbl[0], kbl[1]);
        }
        #pragma unroll
        for (int mi = 0; mi < 4; mi++) {
            int r0 = mi * 16 + qrow;
            int c0 = n0 + qcol;
            float v0 = sacc[mi][0] * SCALE_;
            float v1 = sacc[mi][1] * SCALE_;
            float v2 = sacc[mi][2] * SCALE_;
            float v3 = sacc[mi][3] * SCALE_;
            if (selfb) {
                if (c0 > r0)         v0 = NEG_;
                if (c0 + 1 > r0)     v1 = NEG_;
                if (c0 > r0 + 8)     v2 = NEG_;
                if (c0 + 1 > r0 + 8) v3 = NEG_;
            }
            *(float2*)&Sx[r0 * 68 + c0]       = make_float2(v0, v1);
            *(float2*)&Sx[(r0 + 8) * 68 + c0] = make_float2(v2, v3);
        }
        __syncthreads();

        {
            const int r = tid >> 2, cg = tid & 3;
            float mold = mrw[r];
            float vals[16];
            float mx = -3.0e38f;
            #pragma unroll
            for (int j = 0; j < 16; j++) {
                vals[j] = Sx[r * 68 + cg * 16 + j];
                mx = fmaxf(mx, vals[j]);
            }
            mx = fmaxf(mx, __shfl_xor_sync(0xffffffffu, mx, 1));
            mx = fmaxf(mx, __shfl_xor_sync(0xffffffffu, mx, 2));
            float mnew = fmaxf(mold, mx);
            float al = __expf(mold - mnew);
            float ls = 0.f;
            #pragma unroll
            for (int j = 0; j < 16; j++) {
                float p = __expf(vals[j] - mnew);
                ls += p;
                __nv_bfloat16 phv = __float2bfloat16_rn(p);
                Ph[r * 72 + cg * 16 + j] = phv;
                Pl[r * 72 + cg * 16 + j] =
                    __float2bfloat16_rn(p - __bfloat162float(phv));
            }
            ls += __shfl_xor_sync(0xffffffffu, ls, 1);
            ls += __shfl_xor_sync(0xffffffffu, ls, 2);
            if (cg == 0) {
                mrw[r] = mnew;
                lrw[r] = lrw[r] * al + ls;
                alf[r] = al;
            }
        }
        __syncthreads();

        {
            float al0 = alf[miw * 16 + qrow];
            float al1 = alf[miw * 16 + qrow + 8];
            #pragma unroll
            for (int nt = 0; nt < 8; nt++) {
                accO[nt][0] *= al0; accO[nt][1] *= al0;
                accO[nt][2] *= al1; accO[nt][3] *= al1;
            }
            #pragma unroll
            for (int kk = 0; kk < 4; kk++) {
                uint32_t ph[4], pl[4];
                uint32_t ap = sb + ((uint32_t)(miw * 16) + arow) * 144 +
                              (uint32_t)(kk * 32) + acolb;
                LDMATRIX_X4(ph[0], ph[1], ph[2], ph[3], ap + OPH);
                LDMATRIX_X4(pl[0], pl[1], pl[2], pl[3], ap + OPL);
                uint32_t vrow = sb + ((uint32_t)(kk * 16) + arow) * 272;
                uint32_t vh[4][4], vl[4][4];
                #pragma unroll
                for (int nj = 0; nj < 4; nj++) {
                    uint32_t ad = vrow + (uint32_t)((nhalf + nj * 16) * 2) + acolb;
                    LDMATRIX_X4T(vh[nj][0], vh[nj][1], vh[nj][2], vh[nj][3], ad + OVH);
                    LDMATRIX_X4T(vl[nj][0], vl[nj][1], vl[nj][2], vl[nj][3], ad + OVL);
                }
                #pragma unroll
                for (int nj = 0; nj < 4; nj++) {
                    MMA_BF16(accO[2 * nj],     ph, vh[nj][0], vh[nj][1]);
                    MMA_BF16(accO[2 * nj + 1], ph, vh[nj][2], vh[nj][3]);
                }
                #pragma unroll
                for (int nj = 0; nj < 4; nj++) {
                    MMA_BF16(accO[2 * nj],     pl, vh[nj][0], vh[nj][1]);
                    MMA_BF16(accO[2 * nj + 1], pl, vh[nj][2], vh[nj][3]);
                }
                #pragma unroll
                for (int nj = 0; nj < 4; nj++) {
                    MMA_BF16(accO[2 * nj],     ph, vl[nj][0], vl[nj][1]);
                    MMA_BF16(accO[2 * nj + 1], ph, vl[nj][2], vl[nj][3]);
                }
            }
        }
    }
    __syncthreads();

    {
        int r0 = miw * 16 + qrow;
        float linv0 = 1.0f / lrw[r0];
        float linv1 = 1.0f / lrw[r0 + 8];
        size_t base0 = (tok0 + r0) * HID_ + h * D_ + nhalf;
        size_t base1 = (tok0 + r0 + 8) * HID_ + h * D_ + nhalf;
        #pragma unroll
        for (int nt = 0; nt < 8; nt++) {
            int cn = nt * 8 + qcol;
            float o0 = accO[nt][0] * linv0, o1 = accO[nt][1] * linv0;
            float o2 = accO[nt][2] * linv1, o3 = accO[nt][3] * linv1;
            __nv_bfloat162 H, L;
            split2(o0, o1, H, L);
            *(__nv_bfloat162*)(outh + base0 + cn) = H;
            *(__nv_bfloat162*)(outl + base0 + cn) = L;
            split2(o2, o3, H, L);
            *(__nv_bfloat162*)(outh + base1 + cn) = H;
            *(__nv_bfloat162*)(outl + base1 + cn) = L;
        }
    }
}

// ---------------------------------------------------------------------------
extern "C" void kernel_launch(void* const* d_in, const int* in_sizes, int n_in,
                              void* d_out, int out_size)
{
    const float* hs = (const float*)d_in[0];
    const float* cs = (const float*)d_in[1];
    const float* sn = (const float*)d_in[2];
    const float* Wq = (const float*)d_in[3];
    const float* Wk = (const float*)d_in[4];
    const float* Wv = (const float*)d_in[5];
    const float* Wo = (const float*)d_in[6];
    float* out = (float*)d_out;

    __nv_bfloat16 *qkh, *qkl, *hsh, *hsl, *w1h, *w1l, *w2h, *w2l, *ath, *atl;
    cudaGetSymbolAddress((void**)&qkh, g_qkv_hi);
    cudaGetSymbolAddress((void**)&qkl, g_qkv_lo);
    cudaGetSymbolAddress((void**)&hsh, g_hs_hi);
    cudaGetSymbolAddress((void**)&hsl, g_hs_lo);
    cudaGetSymbolAddress((void**)&w1h, g_w1_hi);
    cudaGetSymbolAddress((void**)&w1l, g_w1_lo);
    cudaGetSymbolAddress((void**)&w2h, g_w2_hi);
    cudaGetSymbolAddress((void**)&w2l, g_w2_lo);
    cudaGetSymbolAddress((void**)&ath, g_at_hi);
    cudaGetSymbolAddress((void**)&atl, g_at_lo);

    cudaFuncSetAttribute(gemm_bf16x3, cudaFuncAttributeMaxDynamicSharedMemorySize,
                         GEMM_SMEM);
    cudaFuncSetAttribute(attn_kernel, cudaFuncAttributeMaxDynamicSharedMemorySize,
                         ATTN_SMEM);

    const int nHS  = MTOT * HID_;
    const int nWq  = HID_ * HID_;
    const int nWkv = 512 * HID_;

    cvt_kernel<<<nHS / 2048, 256>>>(hs, hsh, hsl, nHS);
    cvt_kernel<<<nWq / 2048, 256>>>(Wq, w1h, w1l, nWq);
    cvt_kernel<<<nWkv / 2048, 256>>>(Wk, w1h + (size_t)2048 * HID_,
                                         w1l + (size_t)2048 * HID_, nWkv);
    cvt_kernel<<<nWkv / 2048, 256>>>(Wv, w1h + (size_t)2560 * HID_,
                                         w1l + (size_t)2560 * HID_, nWkv);
    cvt_kernel<<<nWq / 2048, 256>>>(Wo, w2h, w2l, nWq);

    // QKV projection -> bf16 hi/lo directly
    gemm_bf16x3<<<dim3(QKVN_ / 128, MTOT / 128), 256, GEMM_SMEM>>>(
        hsh, hsl, w1h, w1l, nullptr, qkh, qkl, 1, HID_, QKVN_);

    // RoPE on hi/lo pair
    rope_kernel<<<(MTOT * 20) / 8, 256>>>(qkh, qkl, cs, sn);

    // Attention (cp.async loads, emits bf16 hi/lo)
    attn_kernel<<<dim3(NB_, H_, B_), 256, ATTN_SMEM>>>(qkh, qkl, ath, atl);

    // Output projection -> fp32 out
    gemm_bf16x3<<<dim3(HID_ / 128, MTOT / 128), 256, GEMM_SMEM>>>(
        ath, atl, w2h, w2l, out, nullptr, nullptr, 0, HID_, HID_);
}

// round 17
// speedup vs baseline: 2.2026x; 1.0114x over previous
#include <cuda_runtime.h>
#include <cuda_bf16.h>
#include <math.h>
#include <stdint.h>

#define B_    2
#define T_    4096
#define HID_  2048
#define H_    16
#define HKV_  4
#define D_    128
#define NB_   64
#define QKVN_ 3072
#define SCALE_ 0.088388347648318447f
#define NEG_  (-1.0e9f)
#define MTOT  (B_*T_)   // 8192

// ---------------- scratch ----------------------------------------------------
__device__ __nv_bfloat16 g_qkv_hi[(size_t)MTOT * QKVN_];
__device__ __nv_bfloat16 g_qkv_lo[(size_t)MTOT * QKVN_];
__device__ __nv_bfloat16 g_hs_hi[(size_t)MTOT*HID_];
__device__ __nv_bfloat16 g_hs_lo[(size_t)MTOT*HID_];
__device__ __nv_bfloat16 g_w1_hi[(size_t)QKVN_*HID_];
__device__ __nv_bfloat16 g_w1_lo[(size_t)QKVN_*HID_];
__device__ __nv_bfloat16 g_w2_hi[(size_t)HID_*HID_];
__device__ __nv_bfloat16 g_w2_lo[(size_t)HID_*HID_];
__device__ __nv_bfloat16 g_at_hi[(size_t)MTOT*HID_];
__device__ __nv_bfloat16 g_at_lo[(size_t)MTOT*HID_];

// ---------------- PTX helpers ----------------------------------------------
__device__ __forceinline__ uint32_t smem_u32(const void* p) {
    uint32_t a;
    asm("{ .reg .u64 t; cvta.to.shared.u64 t, %1; cvt.u32.u64 %0, t; }"
        : "=r"(a) : "l"(p));
    return a;
}

#define CP_ASYNC16(dst, src) \
    asm volatile("cp.async.cg.shared.global [%0], [%1], 16;\n" \
                 :: "r"(dst), "l"(src))
#define CP_COMMIT() asm volatile("cp.async.commit_group;\n" ::: "memory")
#define CP_WAIT(n)  asm volatile("cp.async.wait_group %0;\n" :: "n"(n) : "memory")

#define LDMATRIX_X4(r0, r1, r2, r3, addr) \
    asm volatile("ldmatrix.sync.aligned.m8n8.x4.shared.b16 {%0,%1,%2,%3}, [%4];" \
                 : "=r"(r0), "=r"(r1), "=r"(r2), "=r"(r3) : "r"(addr))

#define LDMATRIX_X2(r0, r1, addr) \
    asm volatile("ldmatrix.sync.aligned.m8n8.x2.shared.b16 {%0,%1}, [%2];" \
                 : "=r"(r0), "=r"(r1) : "r"(addr))

#define LDMATRIX_X4T(r0, r1, r2, r3, addr) \
    asm volatile("ldmatrix.sync.aligned.m8n8.x4.trans.shared.b16 {%0,%1,%2,%3}, [%4];" \
                 : "=r"(r0), "=r"(r1), "=r"(r2), "=r"(r3) : "r"(addr))

// non-volatile: register-pure, lets the compiler schedule
#define MMA_BF16(d, a, b0, b1) \
    asm("mma.sync.aligned.m16n8k16.row.col.f32.bf16.bf16.f32 " \
        "{%0,%1,%2,%3}, {%4,%5,%6,%7}, {%8,%9}, {%0,%1,%2,%3};" \
        : "+f"((d)[0]), "+f"((d)[1]), "+f"((d)[2]), "+f"((d)[3]) \
        : "r"((a)[0]), "r"((a)[1]), "r"((a)[2]), "r"((a)[3]), \
          "r"(b0), "r"(b1))

// float4 -> bf16 hi x4 + lo x4
__device__ __forceinline__ void cvt4(float4 v, uint2& H, uint2& L) {
    float a[4] = {v.x, v.y, v.z, v.w};
    __nv_bfloat16 h[4], l[4];
    #pragma unroll
    for (int j = 0; j < 4; j++) {
        h[j] = __float2bfloat16_rn(a[j]);
        l[j] = __float2bfloat16_rn(a[j] - __bfloat162float(h[j]));
    }
    union { __nv_bfloat162 b2[2]; uint2 u; } uh, ul;
    uh.b2[0] = __halves2bfloat162(h[0], h[1]);
    uh.b2[1] = __halves2bfloat162(h[2], h[3]);
    ul.b2[0] = __halves2bfloat162(l[0], l[1]);
    ul.b2[1] = __halves2bfloat162(l[2], l[3]);
    H = uh.u; L = ul.u;
}

__device__ __forceinline__ void split2(float a, float b,
                                       __nv_bfloat162& H, __nv_bfloat162& L) {
    __nv_bfloat16 h0 = __float2bfloat16_rn(a);
    __nv_bfloat16 h1 = __float2bfloat16_rn(b);
    H = __halves2bfloat162(h0, h1);
    L = __halves2bfloat162(__float2bfloat16_rn(a - __bfloat162float(h0)),
                           __float2bfloat16_rn(b - __bfloat162float(h1)));
}

// ---------------------------------------------------------------------------
// fp32 -> bf16 hi + residual lo, 8 elements/thread
// ---------------------------------------------------------------------------
__global__ void cvt_kernel(const float* __restrict__ in,
                           __nv_bfloat16* __restrict__ hi,
                           __nv_bfloat16* __restrict__ lo, int n)
{
    size_t i = ((size_t)blockIdx.x * blockDim.x + threadIdx.x) * 8;
    if (i >= (size_t)n) return;
    uint2 H0, L0, H1, L1;
    cvt4(*(const float4*)(in + i),     H0, L0);
    cvt4(*(const float4*)(in + i + 4), H1, L1);
    *(uint4*)(hi + i) = make_uint4(H0.x, H0.y, H1.x, H1.y);
    *(uint4*)(lo + i) = make_uint4(L0.x, L0.y, L1.x, L1.y);
}

// Merged Wq|Wk|Wv conversion: dest rows [0,2048)=Wq, [2048,2560)=Wk, rest=Wv
__global__ void cvt3_kernel(const float* __restrict__ wq,
                            const float* __restrict__ wk,
                            const float* __restrict__ wv,
                            __nv_bfloat16* __restrict__ hi,
                            __nv_bfloat16* __restrict__ lo)
{
    size_t i = ((size_t)blockIdx.x * blockDim.x + threadIdx.x) * 8;
    int row = (int)(i >> 11);
    const float* src;
    size_t off;
    if (row < 2048)      { src = wq; off = i; }
    else if (row < 2560) { src = wk; off = i - (size_t)2048 * 2048; }
    else                 { src = wv; off = i - (size_t)2560 * 2048; }
    uint2 H0, L0, H1, L1;
    cvt4(*(const float4*)(src + off),     H0, L0);
    cvt4(*(const float4*)(src + off + 4), H1, L1);
    *(uint4*)(hi + i) = make_uint4(H0.x, H0.y, H1.x, H1.y);
    *(uint4*)(lo + i) = make_uint4(L0.x, L0.y, L1.x, L1.y);
}

// ---------------------------------------------------------------------------
// mma.sync bf16 GEMM: C = A*B^T, 3-term hi/lo.  BK=32, 96KB smem, 2 CTAs/SM.
// Epilogue: fp32 (Cf) or bf16 hi/lo (Ch/Cl) selected by bf16out.
// ---------------------------------------------------------------------------
#define GEMM_SMEM (3 * 32768)

__global__ void __launch_bounds__(256, 2) gemm_bf16x3(
    const __nv_bfloat16* __restrict__ Ah, const __nv_bfloat16* __restrict__ Al,
    const __nv_bfloat16* __restrict__ Bh, const __nv_bfloat16* __restrict__ Bl,
    float* __restrict__ Cf,
    __nv_bfloat16* __restrict__ Ch, __nv_bfloat16* __restrict__ Cl,
    int bf16out, int K, int ldc)
{
    extern __shared__ char smem[];
    const int tid  = threadIdx.x;
    const int lane = tid & 31;
    const int wid  = tid >> 5;
    const int m0 = blockIdx.y * 128;
    const int n0 = blockIdx.x * 128;
    const int warpM = (wid >> 2) * 64;
    const int warpN = (wid & 3) * 32;

    const uint32_t sb = smem_u32(smem);

    uint32_t soff[2]; uint32_t grow[2]; uint32_t gcol[2];
    #pragma unroll
    for (int t = 0; t < 2; t++) {
        int idx = tid + t * 256;
        int row = idx >> 2, u = idx & 3;
        soff[t] = (uint32_t)(row * 64 + ((u ^ ((row >> 1) & 3)) << 4));
        grow[t] = (uint32_t)row;
        gcol[t] = (uint32_t)(u * 16);
    }

    const int NCH = K >> 5;
    const size_t rs = (size_t)K * 2;
    const char* pAh = (const char*)(Ah + (size_t)m0 * K);
    const char* pAl = (const char*)(Al + (size_t)m0 * K);
    const char* pBh = (const char*)(Bh + (size_t)n0 * K);
    const char* pBl = (const char*)(Bl + (size_t)n0 * K);

    auto load_chunk = [&](int c) {
        uint32_t base = sb + (uint32_t)(c % 3) * 32768u;
        size_t co = (size_t)c * 64;
        #pragma unroll
        for (int t = 0; t < 2; t++) {
            size_t go = (size_t)grow[t] * rs + co + gcol[t];
            CP_ASYNC16(base +          soff[t], pAh + go);
            CP_ASYNC16(base + 8192u  + soff[t], pAl + go);
            CP_ASYNC16(base + 16384u + soff[t], pBh + go);
            CP_ASYNC16(base + 24576u + soff[t], pBl + go);
        }
        CP_COMMIT();
    };

    const uint32_t arow = (uint32_t)(lane & 15);
    const uint32_t asel = (uint32_t)(lane >> 4);

    float d[4][4][4];
    #pragma unroll
    for (int mi = 0; mi < 4; mi++)
        #pragma unroll
        for (int ni = 0; ni < 4; ni++)
            #pragma unroll
            for (int r = 0; r < 4; r++) d[mi][ni][r] = 0.f;

    load_chunk(0);
    if (NCH > 1) load_chunk(1);
    if (NCH > 2) load_chunk(2);

    for (int c = 0; c < NCH; c++) {
        const int rem = NCH - 1 - c;
        if (rem >= 2)      { CP_WAIT(2); }
        else if (rem == 1) { CP_WAIT(1); }
        else               { CP_WAIT(0); }
        __syncthreads();

        const uint32_t base = sb + (uint32_t)(c % 3) * 32768u;
        #pragma unroll
        for (int kk = 0; kk < 2; kk++) {
            const uint32_t cc = (uint32_t)(kk * 2) + asel;
            uint32_t bh[2][4], bl[2][4];
            #pragma unroll
            for (int np = 0; np < 2; np++) {
                uint32_t r = (uint32_t)(warpN + np * 16) + arow;
                uint32_t off = r * 64 + ((cc ^ ((r >> 1) & 3)) << 4);
                LDMATRIX_X4(bh[np][0], bh[np][1], bh[np][2], bh[np][3],
                            base + 16384u + off);
                LDMATRIX_X4(bl[np][0], bl[np][1], bl[np][2], bl[np][3],
                            base + 24576u + off);
            }
            #pragma unroll
            for (int mi = 0; mi < 4; mi++) {
                uint32_t r = (uint32_t)(warpM + mi * 16) + arow;
                uint32_t off = r * 64 + ((cc ^ ((r >> 1) & 3)) << 4);
                uint32_t ah[4], al2[4];
                LDMATRIX_X4(ah[0], ah[1], ah[2], ah[3], base + off);
                LDMATRIX_X4(al2[0], al2[1], al2[2], al2[3], base + 8192u + off);
                #pragma unroll
                for (int ni = 0; ni < 4; ni++) {
                    const int pj = ni >> 1, j = ni & 1;
                    MMA_BF16(d[mi][ni], ah, bh[pj][j], bh[pj][j + 2]);
                }
                #pragma unroll
                for (int ni = 0; ni < 4; ni++) {
                    const int pj = ni >> 1, j = ni & 1;
                    MMA_BF16(d[mi][ni], al2, bh[pj][j], bh[pj][j + 2]);
                }
                #pragma unroll
                for (int ni = 0; ni < 4; ni++) {
                    const int pj = ni >> 1, j = ni & 1;
                    MMA_BF16(d[mi][ni], ah, bl[pj][j], bl[pj][j + 2]);
                }
            }
        }
        __syncthreads();
        if (c + 3 < NCH) load_chunk(c + 3);
    }

    if (bf16out) {
        #pragma unroll
        for (int mi = 0; mi < 4; mi++) {
            const int r0 = m0 + warpM + mi * 16 + (lane >> 2);
            #pragma unroll
            for (int ni = 0; ni < 4; ni++) {
                const int cn = n0 + warpN + ni * 8 + (lane & 3) * 2;
                __nv_bfloat162 H, L;
                split2(d[mi][ni][0], d[mi][ni][1], H, L);
                *(__nv_bfloat162*)(Ch + (size_t)r0 * ldc + cn) = H;
                *(__nv_bfloat162*)(Cl + (size_t)r0 * ldc + cn) = L;
                split2(d[mi][ni][2], d[mi][ni][3], H, L);
                *(__nv_bfloat162*)(Ch + (size_t)(r0 + 8) * ldc + cn) = H;
                *(__nv_bfloat162*)(Cl + (size_t)(r0 + 8) * ldc + cn) = L;
            }
        }
    } else {
        #pragma unroll
        for (int mi = 0; mi < 4; mi++) {
            const int r0 = m0 + warpM + mi * 16 + (lane >> 2);
            #pragma unroll
            for (int ni = 0; ni < 4; ni++) {
                const int cn = n0 + warpN + ni * 8 + (lane & 3) * 2;
                *(float2*)(Cf + (size_t)r0 * ldc + cn) =
                    make_float2(d[mi][ni][0], d[mi][ni][1]);
                *(float2*)(Cf + (size_t)(r0 + 8) * ldc + cn) =
                    make_float2(d[mi][ni][2], d[mi][ni][3]);
            }
        }
    }
}

// ---------------------------------------------------------------------------
// RoPE in-place on qkv hi/lo pair
// ---------------------------------------------------------------------------
__global__ void rope_kernel(__nv_bfloat16* __restrict__ qh,
                            __nv_bfloat16* __restrict__ ql,
                            const float* __restrict__ cosb,
                            const float* __restrict__ sinb)
{
    const int gw   = (blockIdx.x * blockDim.x + threadIdx.x) >> 5;
    const int lane = threadIdx.x & 31;
    const int tok  = gw / 20;
    const int hh   = gw % 20;
    if (tok >= MTOT) return;

    size_t base = (size_t)tok * QKVN_ +
                  (hh < 16 ? hh * D_ : 2048 + (hh - 16) * D_);
    const float* cr = cosb + (size_t)tok * 64;
    const float* sr = sinb + (size_t)tok * 64;

    float x1 = __bfloat162float(qh[base + lane]) +
               __bfloat162float(ql[base + lane]);
    float x2 = __bfloat162float(qh[base + lane + 32]) +
               __bfloat162float(ql[base + lane + 32]);
    float c1 = cr[lane],  s1 = sr[lane];
    float c2 = cr[lane + 32], s2 = sr[lane + 32];
    float y1 = x1 * c1 - x2 * s1;
    float y2 = x2 * c2 + x1 * s2;

    __nv_bfloat16 h1 = __float2bfloat16_rn(y1);
    __nv_bfloat16 h2 = __float2bfloat16_rn(y2);
    qh[base + lane]      = h1;
    ql[base + lane]      = __float2bfloat16_rn(y1 - __bfloat162float(h1));
    qh[base + lane + 32] = h2;
    ql[base + lane + 32] = __float2bfloat16_rn(y2 - __bfloat162float(h2));
}

// ---------------------------------------------------------------------------
// Tensor-core block-sparse attention, bf16 hi/lo 3-term, fp32 softmax.
// Pipelined: split K/V commit groups, K(i+1) prefetch during softmax/PV,
// V(i) wait deferred until just before PV.
// ---------------------------------------------------------------------------
#define OQH 0
#define OQL 17408
#define OKH 34816
#define OKL 52224
#define OVH 69632
#define OVL 87040
#define OSX 104448          // fp32 [64][68]
#define OPH 121856          // bf16 [64][72]
#define OPL 131072
#define OALF 140288
#define OMRW 140544
#define OLRW 140800
#define ATTN_SMEM 141056

__global__ void __launch_bounds__(256) attn_kernel(
    const __nv_bfloat16* __restrict__ qkvh,
    const __nv_bfloat16* __restrict__ qkvl,
    __nv_bfloat16* __restrict__ outh,
    __nv_bfloat16* __restrict__ outl)
{
    extern __shared__ char smc[];
    const uint32_t sb = smem_u32(smc);
    float* Sx  = (float*)(smc + OSX);
    __nv_bfloat16* Ph = (__nv_bfloat16*)(smc + OPH);
    __nv_bfloat16* Pl = (__nv_bfloat16*)(smc + OPL);
    float* alf = (float*)(smc + OALF);
    float* mrw = (float*)(smc + OMRW);
    float* lrw = (float*)(smc + OLRW);

    const int tid  = threadIdx.x;
    const int lane = tid & 31;
    const int wid  = tid >> 5;
    const int iblk = blockIdx.x;
    const int h    = blockIdx.y;
    const int b    = blockIdx.z;
    const int hk   = h >> 2;
    const size_t tok0 = (size_t)b * T_ + (size_t)iblk * 64;

    // valid key-block schedule: {0} then {start..iblk}, start = max(1, iblk-7)
    const int start = (iblk - 7 > 1) ? iblk - 7 : 1;
    const int cnt   = 1 + ((iblk >= 1) ? (iblk - start + 1) : 0);

    auto issueK = [&](int kb) {
        const size_t ktok = (size_t)b * T_ + (size_t)kb * 64;
        const char* kgh = (const char*)(qkvh + ktok * QKVN_ + 2048 + hk * D_);
        const char* kgl = (const char*)(qkvl + ktok * QKVN_ + 2048 + hk * D_);
        for (int f = tid; f < 1024; f += 256) {
            int r = f >> 4, c16 = (f & 15) * 16;
            uint32_t off = (uint32_t)(r * 272 + c16);
            size_t go = (size_t)r * (QKVN_ * 2) + c16;
            CP_ASYNC16(sb + OKH + off, kgh + go);
            CP_ASYNC16(sb + OKL + off, kgl + go);
        }
        CP_COMMIT();
    };
    auto issueV = [&](int kb) {
        const size_t ktok = (size_t)b * T_ + (size_t)kb * 64;
        const char* vgh = (const char*)(qkvh + ktok * QKVN_ + 2560 + hk * D_);
        const char* vgl = (const char*)(qkvl + ktok * QKVN_ + 2560 + hk * D_);
        for (int f = tid; f < 1024; f += 256) {
            int r = f >> 4, c16 = (f & 15) * 16;
            uint32_t off = (uint32_t)(r * 272 + c16);
            size_t go = (size_t)r * (QKVN_ * 2) + c16;
            CP_ASYNC16(sb + OVH + off, vgh + go);
            CP_ASYNC16(sb + OVL + off, vgl + go);
        }
        CP_COMMIT();
    };
    auto kb_of = [&](int i) -> int {
        int j = (i < cnt - 1) ? i : cnt - 1;     // clamp for prefetch
        return (j == 0) ? 0 : start + j - 1;
    };

    // ---- Q tile (group 1) + K0 (group 2) + V0 (group 3) ----
    {
        const char* qgh = (const char*)(qkvh + tok0 * QKVN_ + h * D_);
        const char* qgl = (const char*)(qkvl + tok0 * QKVN_ + h * D_);
        for (int f = tid; f < 1024; f += 256) {
            int r = f >> 4, c16 = (f & 15) * 16;
            uint32_t off = (uint32_t)(r * 272 + c16);
            size_t go = (size_t)r * (QKVN_ * 2) + c16;
            CP_ASYNC16(sb + OQH + off, qgh + go);
            CP_ASYNC16(sb + OQL + off, qgl + go);
        }
        CP_COMMIT();
    }
    issueK(0);
    issueV(0);
    if (tid < 64) { mrw[tid] = -3.0e38f; lrw[tid] = 0.f; }

    const uint32_t arow  = (uint32_t)(lane & 15);
    const uint32_t acolb = (uint32_t)((lane >> 4) * 16);
    const int qrow = lane >> 2;
    const int qcol = (lane & 3) * 2;

    const int n0 = wid * 8;
    const int miw   = wid >> 1;
    const int nhalf = (wid & 1) * 64;

    float accO[8][4];
    #pragma unroll
    for (int nt = 0; nt < 8; nt++)
        #pragma unroll
        for (int r = 0; r < 4; r++) accO[nt][r] = 0.f;

    for (int i = 0; i < cnt; i++) {
        const int kb = kb_of(i);
        const bool selfb = (kb == iblk);

        CP_WAIT(1);          // Q (first iter) + K(i) complete; V(i) may be in flight
        __syncthreads();

        // ---- QK^T, term-major ----
        float sacc[4][4];
        #pragma unroll
        for (int mi = 0; mi < 4; mi++)
            #pragma unroll
            for (int r = 0; r < 4; r++) sacc[mi][r] = 0.f;

        #pragma unroll
        for (int kk = 0; kk < 8; kk++) {
            uint32_t kbh[2], kbl[2];
            {
                uint32_t r = (uint32_t)(n0 + (lane & 7));
                uint32_t cb = (uint32_t)(kk * 32 + ((lane >> 3) & 1) * 16);
                uint32_t ad = sb + r * 272 + cb;
                LDMATRIX_X2(kbh[0], kbh[1], ad + OKH);
                LDMATRIX_X2(kbl[0], kbl[1], ad + OKL);
            }
            uint32_t qh[4][4], ql[4][4];
            #pragma unroll
            for (int mi = 0; mi < 4; mi++) {
                uint32_t ad = sb + ((uint32_t)(mi * 16) + arow) * 272 +
                              (uint32_t)(kk * 32) + acolb;
                LDMATRIX_X4(qh[mi][0], qh[mi][1], qh[mi][2], qh[mi][3], ad + OQH);
                LDMATRIX_X4(ql[mi][0], ql[mi][1], ql[mi][2], ql[mi][3], ad + OQL);
            }
            #pragma unroll
            for (int mi = 0; mi < 4; mi++) MMA_BF16(sacc[mi], qh[mi], kbh[0], kbh[1]);
            #pragma unroll
            for (int mi = 0; mi < 4; mi++) MMA_BF16(sacc[mi], ql[mi], kbh[0], kbh[1]);
            #pragma unroll
            for (int mi = 0; mi < 4; mi++) MMA_BF16(sacc[mi], qh[mi], kbl[0], kbl[1]);
        }
        #pragma unroll
        for (int mi = 0; mi < 4; mi++) {
            int r0 = mi * 16 + qrow;
            int c0 = n0 + qcol;
            float v0 = sacc[mi][0] * SCALE_;
            float v1 = sacc[mi][1] * SCALE_;
            float v2 = sacc[mi][2] * SCALE_;
            float v3 = sacc[mi][3] * SCALE_;
            if (selfb) {
                if (c0 > r0)         v0 = NEG_;
                if (c0 + 1 > r0)     v1 = NEG_;
                if (c0 > r0 + 8)     v2 = NEG_;
                if (c0 + 1 > r0 + 8) v3 = NEG_;
            }
            *(float2*)&Sx[r0 * 68 + c0]       = make_float2(v0, v1);
            *(float2*)&Sx[(r0 + 8) * 68 + c0] = make_float2(v2, v3);
        }
        __syncthreads();

        // ---- online softmax; emit P as bf16 hi/lo ----
        {
            const int r = tid >> 2, cg = tid & 3;
            float mold = mrw[r];
            float vals[16];
            float mx = -3.0e38f;
            #pragma unroll
            for (int j = 0; j < 16; j++) {
                vals[j] = Sx[r * 68 + cg * 16 + j];
                mx = fmaxf(mx, vals[j]);
            }
            mx = fmaxf(mx, __shfl_xor_sync(0xffffffffu, mx, 1));
            mx = fmaxf(mx, __shfl_xor_sync(0xffffffffu, mx, 2));
            float mnew = fmaxf(mold, mx);
            float al = __expf(mold - mnew);
            float ls = 0.f;
            #pragma unroll
            for (int j = 0; j < 16; j++) {
                float p = __expf(vals[j] - mnew);
                ls += p;
                __nv_bfloat16 phv = __float2bfloat16_rn(p);
                Ph[r * 72 + cg * 16 + j] = phv;
                Pl[r * 72 + cg * 16 + j] =
                    __float2bfloat16_rn(p - __bfloat162float(phv));
            }
            ls += __shfl_xor_sync(0xffffffffu, ls, 1);
            ls += __shfl_xor_sync(0xffffffffu, ls, 2);
            if (cg == 0) {
                mrw[r] = mnew;
                lrw[r] = lrw[r] * al + ls;
                alf[r] = al;
            }
        }
        __syncthreads();

        // K buffer now dead (QK reads finished two syncs ago): prefetch K(i+1)
        issueK(kb_of(i + 1));          // pending: [V(i), K(i+1)]

        CP_WAIT(1);                     // V(i) ready
        __syncthreads();

        // ---- PV, term-major ----
        {
            float al0 = alf[miw * 16 + qrow];
            float al1 = alf[miw * 16 + qrow + 8];
            #pragma unroll
            for (int nt = 0; nt < 8; nt++) {
                accO[nt][0] *= al0; accO[nt][1] *= al0;
                accO[nt][2] *= al1; accO[nt][3] *= al1;
            }
            #pragma unroll
            for (int kk = 0; kk < 4; kk++) {
                uint32_t ph[4], pl[4];
                uint32_t ap = sb + ((uint32_t)(miw * 16) + arow) * 144 +
                              (uint32_t)(kk * 32) + acolb;
                LDMATRIX_X4(ph[0], ph[1], ph[2], ph[3], ap + OPH);
                LDMATRIX_X4(pl[0], pl[1], pl[2], pl[3], ap + OPL);
                uint32_t vrow = sb + ((uint32_t)(kk * 16) + arow) * 272;
                uint32_t vh[4][4], vl[4][4];
                #pragma unroll
                for (int nj = 0; nj < 4; nj++) {
                    uint32_t ad = vrow + (uint32_t)((nhalf + nj * 16) * 2) + acolb;
                    LDMATRIX_X4T(vh[nj][0], vh[nj][1], vh[nj][2], vh[nj][3], ad + OVH);
                    LDMATRIX_X4T(vl[nj][0], vl[nj][1], vl[nj][2], vl[nj][3], ad + OVL);
                }
                #pragma unroll
                for (int nj = 0; nj < 4; nj++) {
                    MMA_BF16(accO[2 * nj],     ph, vh[nj][0], vh[nj][1]);
                    MMA_BF16(accO[2 * nj + 1], ph, vh[nj][2], vh[nj][3]);
                }
                #pragma unroll
                for (int nj = 0; nj < 4; nj++) {
                    MMA_BF16(accO[2 * nj],     pl, vh[nj][0], vh[nj][1]);
                    MMA_BF16(accO[2 * nj + 1], pl, vh[nj][2], vh[nj][3]);
                }
                #pragma unroll
                for (int nj = 0; nj < 4; nj++) {
                    MMA_BF16(accO[2 * nj],     ph, vl[nj][0], vl[nj][1]);
                    MMA_BF16(accO[2 * nj + 1], ph, vl[nj][2], vl[nj][3]);
                }
            }
        }
        __syncthreads();               // all V(i) reads done

        issueV(kb_of(i + 1));          // pending: [K(i+1), V(i+1)]
    }

    CP_WAIT(0);                        // drain trailing prefetches before exit
    __syncthreads();

    {
        int r0 = miw * 16 + qrow;
        float linv0 = 1.0f / lrw[r0];
        float linv1 = 1.0f / lrw[r0 + 8];
        size_t base0 = (tok0 + r0) * HID_ + h * D_ + nhalf;
        size_t base1 = (tok0 + r0 + 8) * HID_ + h * D_ + nhalf;
        #pragma unroll
        for (int nt = 0; nt < 8; nt++) {
            int cn = nt * 8 + qcol;
            float o0 = accO[nt][0] * linv0, o1 = accO[nt][1] * linv0;
            float o2 = accO[nt][2] * linv1, o3 = accO[nt][3] * linv1;
            __nv_bfloat162 H, L;
            split2(o0, o1, H, L);
            *(__nv_bfloat162*)(outh + base0 + cn) = H;
            *(__nv_bfloat162*)(outl + base0 + cn) = L;
            split2(o2, o3, H, L);
            *(__nv_bfloat162*)(outh + base1 + cn) = H;
            *(__nv_bfloat162*)(outl + base1 + cn) = L;
        }
    }
}

// ---------------------------------------------------------------------------
extern "C" void kernel_launch(void* const* d_in, const int* in_sizes, int n_in,
                              void* d_out, int out_size)
{
    const float* hs = (const float*)d_in[0];
    const float* cs = (const float*)d_in[1];
    const float* sn = (const float*)d_in[2];
    const float* Wq = (const float*)d_in[3];
    const float* Wk = (const float*)d_in[4];
    const float* Wv = (const float*)d_in[5];
    const float* Wo = (const float*)d_in[6];
    float* out = (float*)d_out;

    __nv_bfloat16 *qkh, *qkl, *hsh, *hsl, *w1h, *w1l, *w2h, *w2l, *ath, *atl;
    cudaGetSymbolAddress((void**)&qkh, g_qkv_hi);
    cudaGetSymbolAddress((void**)&qkl, g_qkv_lo);
    cudaGetSymbolAddress((void**)&hsh, g_hs_hi);
    cudaGetSymbolAddress((void**)&hsl, g_hs_lo);
    cudaGetSymbolAddress((void**)&w1h, g_w1_hi);
    cudaGetSymbolAddress((void**)&w1l, g_w1_lo);
    cudaGetSymbolAddress((void**)&w2h, g_w2_hi);
    cudaGetSymbolAddress((void**)&w2l, g_w2_lo);
    cudaGetSymbolAddress((void**)&ath, g_at_hi);
    cudaGetSymbolAddress((void**)&atl, g_at_lo);

    cudaFuncSetAttribute(gemm_bf16x3, cudaFuncAttributeMaxDynamicSharedMemorySize,
                         GEMM_SMEM);
    cudaFuncSetAttribute(attn_kernel, cudaFuncAttributeMaxDynamicSharedMemorySize,
                         ATTN_SMEM);

    const int nHS  = MTOT * HID_;
    const int nWq  = HID_ * HID_;
    const int nW1  = QKVN_ * HID_;

    cvt_kernel<<<nHS / 2048, 256>>>(hs, hsh, hsl, nHS);
    cvt3_kernel<<<nW1 / 2048, 256>>>(Wq, Wk, Wv, w1h, w1l);
    cvt_kernel<<<nWq / 2048, 256>>>(Wo, w2h, w2l, nWq);

    // QKV projection -> bf16 hi/lo directly
    gemm_bf16x3<<<dim3(QKVN_ / 128, MTOT / 128), 256, GEMM_SMEM>>>(
        hsh, hsl, w1h, w1l, nullptr, qkh, qkl, 1, HID_, QKVN_);

    // RoPE on hi/lo pair
    rope_kernel<<<(MTOT * 20) / 8, 256>>>(qkh, qkl, cs, sn);

    // Attention (pipelined cp.async, emits bf16 hi/lo)
    attn_kernel<<<dim3(NB_, H_, B_), 256, ATTN_SMEM>>>(qkh, qkl, ath, atl);

    // Output projection -> fp32 out
    gemm_bf16x3<<<dim3(HID_ / 128, MTOT / 128), 256, GEMM_SMEM>>>(
        ath, atl, w2h, w2l, out, nullptr, nullptr, 0, HID_, HID_);
}